// round 1
// baseline (speedup 1.0000x reference)
#include <cuda_runtime.h>
#include <math.h>

#define Nn 10000
#define Ee 160000
#define Gg 100
#define Ll 5

// ---------------- scratch (device globals: no allocation allowed) ----------------
__device__ float g_feat [Nn*128];
__device__ float g_featA[Nn*128];
__device__ float g_featB[Nn*128];
__device__ float g_tmp  [Nn*128];
__device__ float g_sh   [Nn*9];
__device__ float g_pos  [Nn*3];
__device__ float g_msum [Nn*128];
__device__ float g_psum [Nn*3];
__device__ float g_ssum [Nn*9];
__device__ float g_deg  [Nn];
__device__ float g_com  [Gg*3];
__device__ float g_cnt  [Gg];
__device__ float g_P1   [10*128];
__device__ float g_P2   [10*128];
__device__ float g_cmsg [10];
__device__ float g_h    [(size_t)Ee*128];
__device__ float g_m    [(size_t)Ee*128];
__device__ float g_pool [Gg*140];

__device__ __forceinline__ float silu_f(float x) { return x / (1.0f + __expf(-x)); }

__device__ __forceinline__ void sph2(float vx, float vy, float vz, float* o) {
    const float S3  = 1.7320508075688772f;
    const float HS3 = 0.8660254037844386f;
    float r = sqrtf(vx*vx + vy*vy + vz*vz);
    float inv = 1.0f / fmaxf(r, 1e-12f);
    float x = vx*inv, y = vy*inv, z = vz*inv;
    o[0] = S3*x*z;
    o[1] = S3*x*y;
    o[2] = y*y - 0.5f*(x*x + z*z);
    o[3] = S3*y*z;
    o[4] = HS3*(z*z - x*x);
}

// ---------------- shared-mem GEMM core: 64 rows x 128 cols, K=128 ----------------
// As: row-major, stride 132 (padded).  Ws: row-major [k][c], stride 128.
// Thread map: 256 threads, tx=tid&15 (8 cols), ty=tid>>4 (4 rows).
#define FMA8(I, AV) \
    acc[I][0]=fmaf(AV,w0.x,acc[I][0]); acc[I][1]=fmaf(AV,w0.y,acc[I][1]); \
    acc[I][2]=fmaf(AV,w0.z,acc[I][2]); acc[I][3]=fmaf(AV,w0.w,acc[I][3]); \
    acc[I][4]=fmaf(AV,w1.x,acc[I][4]); acc[I][5]=fmaf(AV,w1.y,acc[I][5]); \
    acc[I][6]=fmaf(AV,w1.z,acc[I][6]); acc[I][7]=fmaf(AV,w1.w,acc[I][7]);

__device__ __forceinline__ void mm_tile(const float* __restrict__ As,
                                        const float* __restrict__ Ws,
                                        int r0, int c0, float acc[4][8]) {
    #pragma unroll
    for (int i = 0; i < 4; i++)
        #pragma unroll
        for (int j = 0; j < 8; j++) acc[i][j] = 0.0f;

    for (int k = 0; k < 128; k += 4) {
        float ar[4][4];
        #pragma unroll
        for (int i = 0; i < 4; i++)
            *(float4*)&ar[i][0] = *(const float4*)(As + (r0 + i)*132 + k);
        #pragma unroll
        for (int kk = 0; kk < 4; kk++) {
            const float* wr = Ws + (k + kk)*128 + c0;
            float4 w0 = *(const float4*)(wr);
            float4 w1 = *(const float4*)(wr + 4);
            float av0 = ar[0][kk], av1 = ar[1][kk], av2 = ar[2][kk], av3 = ar[3][kk];
            FMA8(0, av0) FMA8(1, av1) FMA8(2, av2) FMA8(3, av3)
        }
    }
}

// Generic GEMM: C[M x 128] = act( A[M x 128] @ W[128 x 128] (+Cin) (+bias) )
#define GEMM_SMEM_BYTES ((64*132 + 128*128)*4)
__global__ void __launch_bounds__(256)
gemm_kernel(const float* __restrict__ A, const float* __restrict__ W,
            const float* __restrict__ bias, const float* __restrict__ Cin,
            float* __restrict__ C, int M, int act) {
    extern __shared__ float sm[];
    float* As = sm;             // 64*132
    float* Ws = sm + 64*132;    // 128*128
    int tid = threadIdx.x;
    int row0 = blockIdx.x * 64;

    for (int idx = tid; idx < 64*32; idx += 256) {
        int r = idx >> 5, c4 = (idx & 31) * 4;
        float4 v = make_float4(0.f, 0.f, 0.f, 0.f);
        if (row0 + r < M) v = *(const float4*)(A + (size_t)(row0 + r)*128 + c4);
        *(float4*)(As + r*132 + c4) = v;
    }
    for (int idx = tid; idx < 128*32; idx += 256) {
        int k = idx >> 5, c4 = (idx & 31) * 4;
        *(float4*)(Ws + k*128 + c4) = *(const float4*)(W + k*128 + c4);
    }
    __syncthreads();

    int tx = tid & 15, ty = tid >> 4;
    int c0 = tx * 8, r0 = ty * 4;
    float acc[4][8];
    mm_tile(As, Ws, r0, c0, acc);

    #pragma unroll
    for (int i = 0; i < 4; i++) {
        int r = row0 + r0 + i;
        if (r >= M) continue;
        #pragma unroll
        for (int j = 0; j < 8; j++) {
            int c = c0 + j;
            float v = acc[i][j];
            if (Cin)  v += Cin[(size_t)r*128 + c];
            if (bias) v += bias[c];
            if (act)  v = silu_f(v);
            C[(size_t)r*128 + c] = v;
        }
    }
}

// ---------------- init kernels ----------------
__global__ void node_init_kernel(const int* __restrict__ atoms, const float* __restrict__ emb) {
    int idx = blockIdx.x*256 + threadIdx.x;      // N*128 threads
    int i = idx >> 7, d = idx & 127;
    g_feat[idx] = emb[atoms[i]*128 + d];
}

__global__ void com_kernel(const int* __restrict__ batch) {
    int i = blockIdx.x*256 + threadIdx.x;
    if (i >= Nn) return;
    int b = batch[i];
    atomicAdd(&g_com[b*3+0], g_pos[i*3+0]);
    atomicAdd(&g_com[b*3+1], g_pos[i*3+1]);
    atomicAdd(&g_com[b*3+2], g_pos[i*3+2]);
    atomicAdd(&g_cnt[b], 1.0f);
}

__global__ void deg_kernel(const int* __restrict__ ei) {
    int e = blockIdx.x*256 + threadIdx.x;
    if (e >= Ee) return;
    atomicAdd(&g_deg[ei[e]], 1.0f);
}

// per-vocab projections + node-center msg (only output channel 2 survives)
__global__ void vocab_kernel(const float* __restrict__ emb, const float* __restrict__ Wsi1,
                             const float* __restrict__ WsiC1, const float* __restrict__ bsiC1,
                             const float* __restrict__ WsiC2, const float* __restrict__ bsiC2) {
    __shared__ float es[128];
    __shared__ float redv[128];
    int v = blockIdx.x, j = threadIdx.x;
    es[j] = emb[v*128 + j];
    __syncthreads();
    float p1 = 0.f, p2 = 0.f, hc = 0.f;
    for (int k = 0; k < 128; k++) {
        float e = es[k];
        p1 = fmaf(e, Wsi1[(1 + k)*128 + j], p1);
        p2 = fmaf(e, Wsi1[(129 + k)*128 + j], p2);
        hc = fmaf(e, WsiC1[k*128 + j], hc);
    }
    g_P1[v*128 + j] = p1;
    g_P2[v*128 + j] = p2;
    hc = silu_f(hc + bsiC1[j]);
    redv[j] = hc * WsiC2[j*3 + 2];
    __syncthreads();
    for (int s = 64; s > 0; s >>= 1) {
        if (j < s) redv[j] += redv[j + s];
        __syncthreads();
    }
    if (j == 0) g_cmsg[v] = redv[0] + bsiC2[2];
}

// initial edge MLP (warp per edge): accumulate l=2 sh contribution into g_ssum
__global__ void edge_init_kernel(const int* __restrict__ ei, const int* __restrict__ atoms,
                                 const float* __restrict__ Wsi1, const float* __restrict__ bsi1,
                                 const float* __restrict__ Wsi2, const float* __restrict__ bsi2) {
    int e = blockIdx.x*8 + (threadIdx.x >> 5);
    int lane = threadIdx.x & 31;
    int r = ei[e], c = ei[Ee + e];
    float dp0 = g_pos[r*3+0] - g_pos[c*3+0];
    float dp1 = g_pos[r*3+1] - g_pos[c*3+1];
    float dp2 = g_pos[r*3+2] - g_pos[c*3+2];
    float dist = sqrtf(dp0*dp0 + dp1*dp1 + dp2*dp2);
    int ar = atoms[r], ac = atoms[c];
    float partial = 0.f;
    #pragma unroll
    for (int q = 0; q < 4; q++) {
        int d = lane + q*32;
        float h = silu_f(dist*Wsi1[d] + g_P1[ar*128 + d] + g_P2[ac*128 + d] + bsi1[d]);
        partial = fmaf(h, Wsi2[d*3 + 2], partial);
    }
    #pragma unroll
    for (int off = 16; off > 0; off >>= 1)
        partial += __shfl_xor_sync(0xffffffffu, partial, off);
    if (lane == 0) {
        float msg2 = partial + bsi2[2];
        float y2[5];
        sph2(dp0, dp1, dp2, y2);
        #pragma unroll
        for (int q = 0; q < 5; q++)
            atomicAdd(&g_ssum[r*9 + 4 + q], y2[q]*msg2);
    }
}

__global__ void sh_init_kernel(const int* __restrict__ atoms, const int* __restrict__ batch) {
    int i = blockIdx.x*256 + threadIdx.x;
    if (i >= Nn) return;
    float dg = fmaxf(g_deg[i], 1.0f);
    int b = batch[i];
    float cn = fmaxf(g_cnt[b], 1.0f);
    float vx = g_pos[i*3+0] - g_com[b*3+0]/cn;
    float vy = g_pos[i*3+1] - g_com[b*3+1]/cn;
    float vz = g_pos[i*3+2] - g_com[b*3+2]/cn;
    float y2[5];
    sph2(vx, vy, vz, y2);
    float cm = g_cmsg[atoms[i]];
    #pragma unroll
    for (int q = 0; q < 4; q++) g_sh[i*9 + q] = 0.0f;
    #pragma unroll
    for (int q = 0; q < 5; q++)
        g_sh[i*9 + 4 + q] = g_ssum[i*9 + 4 + q]/dg + cm*y2[q];
}

// ---------------- per-layer edge kernels ----------------
// h = silu(featA[row] + featB[col] + d2*Wt[0] + ip0*Wt[1] + ip1*Wt[2] + ip2*Wt[3] + bm1)
__global__ void edge_h_kernel(const int* __restrict__ ei, const float* __restrict__ Wt,
                              const float* __restrict__ bm1l) {
    int e = blockIdx.x*8 + (threadIdx.x >> 5);
    int lane = threadIdx.x & 31;
    int r = ei[e], c = ei[Ee + e];
    float dp0 = g_pos[r*3+0] - g_pos[c*3+0];
    float dp1 = g_pos[r*3+1] - g_pos[c*3+1];
    float dp2 = g_pos[r*3+2] - g_pos[c*3+2];
    float d2 = dp0*dp0 + dp1*dp1 + dp2*dp2;
    float t = 0.f;
    if (lane < 9) t = g_sh[r*9 + lane] * g_sh[c*9 + lane];
    float ip0 = __shfl_sync(0xffffffffu, t, 0);
    float ip1 = __shfl_sync(0xffffffffu, t, 1) + __shfl_sync(0xffffffffu, t, 2)
              + __shfl_sync(0xffffffffu, t, 3);
    float ip2 = __shfl_sync(0xffffffffu, t, 4) + __shfl_sync(0xffffffffu, t, 5)
              + __shfl_sync(0xffffffffu, t, 6) + __shfl_sync(0xffffffffu, t, 7)
              + __shfl_sync(0xffffffffu, t, 8);
    #pragma unroll
    for (int q = 0; q < 4; q++) {
        int d = lane + q*32;
        float v = g_featA[(size_t)r*128 + d] + g_featB[(size_t)c*128 + d]
                + d2*Wt[d] + ip0*Wt[128 + d] + ip1*Wt[256 + d] + ip2*Wt[384 + d]
                + bm1l[d];
        g_h[(size_t)e*128 + d] = silu_f(v);
    }
}

// fused: p-scalar MLP + s MLP + all scatters, 64 edges/block
#define EP_SMEM_FLOATS (64*132 + 128*128 + 3*64*16 + 128 + 384 + 256)
#define EP_SMEM_BYTES  (EP_SMEM_FLOATS*4 + 128*4)
__global__ void __launch_bounds__(256)
edge_post_kernel(const int* __restrict__ ei,
                 const float* __restrict__ Wp1, const float* __restrict__ bp1,
                 const float* __restrict__ Wp2, const float* __restrict__ bp2,
                 const float* __restrict__ Ws1, const float* __restrict__ bs1,
                 const float* __restrict__ Ws2, const float* __restrict__ bs2) {
    extern __shared__ float sm[];
    float* m_s  = sm;                    // 64*132
    float* W_s  = m_s  + 64*132;         // 128*128
    float* red  = W_s  + 128*128;        // 3*64*16
    float* bh   = red  + 3*64*16;        // 128
    float* w2s  = bh   + 128;            // 128*3
    float* outs = w2s  + 384;            // 64*4
    int*   ridx = (int*)(outs + 256);    // 64
    int*   cidx = ridx + 64;             // 64

    int tid = threadIdx.x;
    int e0 = blockIdx.x * 64;
    if (tid < 64) {
        ridx[tid] = ei[e0 + tid];
        cidx[tid] = ei[Ee + e0 + tid];
    }
    for (int idx = tid; idx < 64*32; idx += 256) {
        int r = idx >> 5, c4 = (idx & 31) * 4;
        *(float4*)(m_s + r*132 + c4) = *(const float4*)(g_m + (size_t)(e0 + r)*128 + c4);
    }
    // pass 1: Wp1 -> pscal
    for (int idx = tid; idx < 128*32; idx += 256) {
        int k = idx >> 5, c4 = (idx & 31) * 4;
        *(float4*)(W_s + k*128 + c4) = *(const float4*)(Wp1 + k*128 + c4);
    }
    if (tid < 128) { bh[tid] = bp1[tid]; w2s[tid] = Wp2[tid]; }
    __syncthreads();

    int tx = tid & 15, ty = tid >> 4;
    int c0 = tx * 8, r0 = ty * 4;
    {
        float acc[4][8];
        mm_tile(m_s, W_s, r0, c0, acc);
        #pragma unroll
        for (int i = 0; i < 4; i++) {
            float part = 0.f;
            #pragma unroll
            for (int j = 0; j < 8; j++) {
                int c = c0 + j;
                part = fmaf(silu_f(acc[i][j] + bh[c]), w2s[c], part);
            }
            red[(r0 + i)*16 + tx] = part;
        }
    }
    __syncthreads();
    if (tid < 64) {
        float s = 0.f;
        #pragma unroll
        for (int x = 0; x < 16; x++) s += red[tid*16 + x];
        outs[tid*4 + 0] = s + bp2[0];
    }
    // pass 2: Ws1 -> sout[3]
    for (int idx = tid; idx < 128*32; idx += 256) {
        int k = idx >> 5, c4 = (idx & 31) * 4;
        *(float4*)(W_s + k*128 + c4) = *(const float4*)(Ws1 + k*128 + c4);
    }
    if (tid < 128) {
        bh[tid] = bs1[tid];
        w2s[tid*3+0] = Ws2[tid*3+0];
        w2s[tid*3+1] = Ws2[tid*3+1];
        w2s[tid*3+2] = Ws2[tid*3+2];
    }
    __syncthreads();
    {
        float acc[4][8];
        mm_tile(m_s, W_s, r0, c0, acc);
        float part[4][3];
        #pragma unroll
        for (int i = 0; i < 4; i++) { part[i][0]=0.f; part[i][1]=0.f; part[i][2]=0.f; }
        #pragma unroll
        for (int i = 0; i < 4; i++)
            #pragma unroll
            for (int j = 0; j < 8; j++) {
                int c = c0 + j;
                float hv = silu_f(acc[i][j] + bh[c]);
                part[i][0] = fmaf(hv, w2s[c*3+0], part[i][0]);
                part[i][1] = fmaf(hv, w2s[c*3+1], part[i][1]);
                part[i][2] = fmaf(hv, w2s[c*3+2], part[i][2]);
            }
        #pragma unroll
        for (int t = 0; t < 3; t++)
            #pragma unroll
            for (int i = 0; i < 4; i++)
                red[t*1024 + (r0 + i)*16 + tx] = part[i][t];
    }
    __syncthreads();
    if (tid < 64) {
        #pragma unroll
        for (int t = 0; t < 3; t++) {
            float s = 0.f;
            #pragma unroll
            for (int x = 0; x < 16; x++) s += red[t*1024 + tid*16 + x];
            outs[tid*4 + 1 + t] = s + bs2[t];
        }
    }
    __syncthreads();
    // scatter: p_sum / s_sum (1 thread per edge)
    if (tid < 64) {
        int r = ridx[tid], c = cidx[tid];
        float psc = outs[tid*4 + 0];
        float s0 = outs[tid*4 + 1], s1 = outs[tid*4 + 2], s2 = outs[tid*4 + 3];
        float dp0 = g_pos[r*3+0] - g_pos[c*3+0];
        float dp1 = g_pos[r*3+1] - g_pos[c*3+1];
        float dp2 = g_pos[r*3+2] - g_pos[c*3+2];
        atomicAdd(&g_psum[r*3+0], dp0*psc);
        atomicAdd(&g_psum[r*3+1], dp1*psc);
        atomicAdd(&g_psum[r*3+2], dp2*psc);
        #pragma unroll
        for (int q = 0; q < 9; q++) {
            float diff = g_sh[r*9 + q] - g_sh[c*9 + q];
            float w = (q == 0) ? s0 : (q < 4) ? s1 : s2;
            atomicAdd(&g_ssum[r*9 + q], diff*w);
        }
    }
    // scatter: m_sum (4 threads per edge)
    {
        int ee = tid >> 2, part = tid & 3;
        int r = ridx[ee];
        #pragma unroll
        for (int d = part*32; d < part*32 + 32; d++)
            atomicAdd(&g_msum[(size_t)r*128 + d], m_s[ee*132 + d]);
    }
}

__global__ void divm_kernel() {
    int idx = blockIdx.x*256 + threadIdx.x;   // N*128
    g_msum[idx] /= fmaxf(g_deg[idx >> 7], 1.0f);
}

__global__ void posh_kernel() {
    int i = blockIdx.x*256 + threadIdx.x;
    if (i >= Nn) return;
    float inv = 1.0f / fmaxf(g_deg[i], 1.0f);
    #pragma unroll
    for (int q = 0; q < 3; q++) g_pos[i*3 + q] += g_psum[i*3 + q]*inv;
    #pragma unroll
    for (int q = 0; q < 9; q++) g_sh[i*9 + q] += g_ssum[i*9 + q]*inv;
}

// ---------------- readout ----------------
__global__ void pool_kernel(const int* __restrict__ batch) {
    int idx = blockIdx.x*256 + threadIdx.x;
    if (idx >= Nn*140) return;
    int i = idx / 140, c = idx % 140;
    float v;
    if (c < 128)      v = g_feat[(size_t)i*128 + c];
    else if (c < 131) v = g_pos[i*3 + (c - 128)];
    else              v = g_sh[i*9 + (c - 131)];
    atomicAdd(&g_pool[batch[i]*140 + c], v);
}

__global__ void pred_kernel(const float* __restrict__ Wpred, const float* __restrict__ bpred,
                            float* __restrict__ out) {
    int g = blockIdx.x, lane = threadIdx.x;
    float s = 0.f;
    for (int c = lane; c < 140; c += 32)
        s = fmaf(g_pool[g*140 + c], Wpred[c], s);
    #pragma unroll
    for (int off = 16; off > 0; off >>= 1)
        s += __shfl_xor_sync(0xffffffffu, s, off);
    if (lane == 0) out[g] = s + bpred[0];
}

// ---------------- host ----------------
extern "C" void kernel_launch(void* const* d_in, const int* in_sizes, int n_in,
                              void* d_out, int out_size) {
    const int*   atoms = (const int*)d_in[0];
    const int*   ei    = (const int*)d_in[1];
    const int*   batch = (const int*)d_in[2];
    const float* pos   = (const float*)d_in[3];
    const float* emb   = (const float*)d_in[4];
    const float* Wsi1  = (const float*)d_in[5];  const float* bsi1  = (const float*)d_in[6];
    const float* Wsi2  = (const float*)d_in[7];  const float* bsi2  = (const float*)d_in[8];
    const float* WsiC1 = (const float*)d_in[9];  const float* bsiC1 = (const float*)d_in[10];
    const float* WsiC2 = (const float*)d_in[11]; const float* bsiC2 = (const float*)d_in[12];
    const float* Wm1   = (const float*)d_in[13]; const float* bm1   = (const float*)d_in[14];
    const float* Wm2   = (const float*)d_in[15]; const float* bm2   = (const float*)d_in[16];
    const float* Wp1   = (const float*)d_in[17]; const float* bp1   = (const float*)d_in[18];
    const float* Wp2   = (const float*)d_in[19]; const float* bp2   = (const float*)d_in[20];
    const float* Wn1   = (const float*)d_in[21]; const float* bn1   = (const float*)d_in[22];
    const float* Wn2   = (const float*)d_in[23]; const float* bn2   = (const float*)d_in[24];
    const float* Ws1   = (const float*)d_in[25]; const float* bs1   = (const float*)d_in[26];
    const float* Ws2   = (const float*)d_in[27]; const float* bs2   = (const float*)d_in[28];
    const float* Wpred = (const float*)d_in[29]; const float* bpred = (const float*)d_in[30];
    float* out = (float*)d_out;

    cudaFuncSetAttribute(gemm_kernel, cudaFuncAttributeMaxDynamicSharedMemorySize, GEMM_SMEM_BYTES);
    cudaFuncSetAttribute(edge_post_kernel, cudaFuncAttributeMaxDynamicSharedMemorySize, EP_SMEM_BYTES);

    void *p_msum, *p_psum, *p_ssum, *p_deg, *p_com, *p_cnt, *p_pool, *p_pos;
    void *p_feat, *p_featA, *p_featB, *p_tmp, *p_h, *p_m;
    cudaGetSymbolAddress(&p_msum, g_msum);
    cudaGetSymbolAddress(&p_psum, g_psum);
    cudaGetSymbolAddress(&p_ssum, g_ssum);
    cudaGetSymbolAddress(&p_deg,  g_deg);
    cudaGetSymbolAddress(&p_com,  g_com);
    cudaGetSymbolAddress(&p_cnt,  g_cnt);
    cudaGetSymbolAddress(&p_pool, g_pool);
    cudaGetSymbolAddress(&p_pos,  g_pos);
    cudaGetSymbolAddress(&p_feat,  g_feat);
    cudaGetSymbolAddress(&p_featA, g_featA);
    cudaGetSymbolAddress(&p_featB, g_featB);
    cudaGetSymbolAddress(&p_tmp,   g_tmp);
    cudaGetSymbolAddress(&p_h,     g_h);
    cudaGetSymbolAddress(&p_m,     g_m);

    cudaMemsetAsync(p_deg,  0, Nn*4, 0);
    cudaMemsetAsync(p_com,  0, Gg*3*4, 0);
    cudaMemsetAsync(p_cnt,  0, Gg*4, 0);
    cudaMemsetAsync(p_ssum, 0, Nn*9*4, 0);
    cudaMemsetAsync(p_pool, 0, Gg*140*4, 0);
    cudaMemcpyAsync(p_pos, pos, Nn*3*4, cudaMemcpyDeviceToDevice, 0);

    node_init_kernel<<<(Nn*128)/256, 256>>>(atoms, emb);
    com_kernel<<<(Nn + 255)/256, 256>>>(batch);
    deg_kernel<<<(Ee + 255)/256, 256>>>(ei);
    vocab_kernel<<<10, 128>>>(emb, Wsi1, WsiC1, bsiC1, WsiC2, bsiC2);
    edge_init_kernel<<<Ee/8, 256>>>(ei, atoms, Wsi1, bsi1, Wsi2, bsi2);
    sh_init_kernel<<<(Nn + 255)/256, 256>>>(atoms, batch);

    int gridN = (Nn + 63)/64;   // 157
    int gridE = Ee/64;          // 2500

    for (int l = 0; l < Ll; l++) {
        cudaMemsetAsync(p_msum, 0, (size_t)Nn*128*4, 0);
        cudaMemsetAsync(p_psum, 0, Nn*3*4, 0);
        cudaMemsetAsync(p_ssum, 0, Nn*9*4, 0);

        // node-level factorization of the edge-MLP input layer
        gemm_kernel<<<gridN, 256, GEMM_SMEM_BYTES>>>(
            (const float*)p_feat, Wm1 + (size_t)l*260*128, nullptr, nullptr,
            (float*)p_featA, Nn, 0);
        gemm_kernel<<<gridN, 256, GEMM_SMEM_BYTES>>>(
            (const float*)p_feat, Wm1 + ((size_t)l*260 + 128)*128, nullptr, nullptr,
            (float*)p_featB, Nn, 0);

        edge_h_kernel<<<Ee/8, 256>>>(ei, Wm1 + ((size_t)l*260 + 256)*128, bm1 + l*128);

        gemm_kernel<<<gridE, 256, GEMM_SMEM_BYTES>>>(
            (const float*)p_h, Wm2 + (size_t)l*128*128, bm2 + l*128, nullptr,
            (float*)p_m, Ee, 1);

        edge_post_kernel<<<gridE, 256, EP_SMEM_BYTES>>>(
            ei,
            Wp1 + (size_t)l*128*128, bp1 + l*128, Wp2 + l*128, bp2 + l,
            Ws1 + (size_t)l*128*128, bs1 + l*128, Ws2 + l*384, bs2 + l*3);

        divm_kernel<<<(Nn*128)/256, 256>>>();
        posh_kernel<<<(Nn + 255)/256, 256>>>();

        // node update MLP
        gemm_kernel<<<gridN, 256, GEMM_SMEM_BYTES>>>(
            (const float*)p_feat, Wn1 + (size_t)l*256*128, nullptr, nullptr,
            (float*)p_tmp, Nn, 0);
        gemm_kernel<<<gridN, 256, GEMM_SMEM_BYTES>>>(
            (const float*)p_msum, Wn1 + ((size_t)l*256 + 128)*128, bn1 + l*128,
            (const float*)p_tmp, (float*)p_tmp, Nn, 1);
        gemm_kernel<<<gridN, 256, GEMM_SMEM_BYTES>>>(
            (const float*)p_tmp, Wn2 + (size_t)l*128*128, bn2 + l*128, nullptr,
            (float*)p_feat, Nn, 0);
    }

    pool_kernel<<<(Nn*140 + 255)/256, 256>>>(batch);
    pred_kernel<<<Gg, 32>>>(Wpred, bpred, out);
}

// round 2
// speedup vs baseline: 1.2184x; 1.2184x over previous
#include <cuda_runtime.h>
#include <math.h>

#define Nn 10000
#define Ee 160000
#define Gg 100
#define Ll 5

typedef unsigned long long u64;

// ---------------- scratch (device globals: no allocation allowed) ----------------
__device__ float g_feat [Nn*128];
__device__ float g_featA[Nn*128];
__device__ float g_featB[Nn*128];
__device__ float g_tmp  [Nn*128];
__device__ float g_sh   [Nn*9];
__device__ float g_pos  [Nn*3];
__device__ float g_msum [Nn*128];
__device__ float g_psum [Nn*3];
__device__ float g_ssum [Nn*9];
__device__ float g_deg  [Nn];
__device__ float g_com  [Gg*3];
__device__ float g_cnt  [Gg];
__device__ float g_P1   [10*128];
__device__ float g_P2   [10*128];
__device__ float g_cmsg [10];
__device__ float g_pool [Gg*140];
// pre-transposed weights: 5 layers x 8 slots x [128 cols][132 (128 k + pad)]
__device__ float g_Wt   [Ll*8*128*132];

__device__ __forceinline__ float silu_f(float x) { return x / (1.0f + __expf(-x)); }

__device__ __forceinline__ void sph2(float vx, float vy, float vz, float* o) {
    const float S3  = 1.7320508075688772f;
    const float HS3 = 0.8660254037844386f;
    float r = sqrtf(vx*vx + vy*vy + vz*vz);
    float inv = 1.0f / fmaxf(r, 1e-12f);
    float x = vx*inv, y = vy*inv, z = vz*inv;
    o[0] = S3*x*z;
    o[1] = S3*x*y;
    o[2] = y*y - 0.5f*(x*x + z*z);
    o[3] = S3*y*z;
    o[4] = HS3*(z*z - x*x);
}

// ---------------- packed f32x2 GEMM core ----------------
__device__ __forceinline__ u64 fma2(u64 a, u64 b, u64 c) {
    u64 d;
    asm("fma.rn.f32x2 %0, %1, %2, %3;" : "=l"(d) : "l"(a), "l"(b), "l"(c));
    return d;
}
__device__ __forceinline__ float pairsum(u64 v) {
    float lo = __uint_as_float((unsigned)(v & 0xffffffffull));
    float hi = __uint_as_float((unsigned)(v >> 32));
    return lo + hi;
}

// As: [rows][132] row-major tile (rows 0..63).  Wt: [col][132] transposed weights.
// Thread (tx=tid&15, ty=tid>>4): rows r0=ty*4..+3, cols c_j = tx + 16*j, j=0..7.
// acc[i][j] packs {sum over even k, sum over odd k}.
__device__ __forceinline__ void mm2(const float* __restrict__ As,
                                    const float* __restrict__ Wt,
                                    int r0, int tx, u64 acc[4][8]) {
    #pragma unroll
    for (int i = 0; i < 4; i++)
        #pragma unroll
        for (int j = 0; j < 8; j++) acc[i][j] = 0ull;

    const float* ap = As + r0*132;
    const float* wp = Wt + tx*132;

    #pragma unroll 2
    for (int k = 0; k < 128; k += 4) {
        ulonglong2 a[4], b[8];
        #pragma unroll
        for (int i = 0; i < 4; i++)
            a[i] = *(const ulonglong2*)(ap + i*132 + k);
        #pragma unroll
        for (int j = 0; j < 8; j++)
            b[j] = *(const ulonglong2*)(wp + j*16*132 + k);
        #pragma unroll
        for (int i = 0; i < 4; i++)
            #pragma unroll
            for (int j = 0; j < 8; j++)
                acc[i][j] = fma2(a[i].x, b[j].x, acc[i][j]);
        #pragma unroll
        for (int i = 0; i < 4; i++)
            #pragma unroll
            for (int j = 0; j < 8; j++)
                acc[i][j] = fma2(a[i].y, b[j].y, acc[i][j]);
    }
}

// ---------------- weight pre-transpose (once per launch) ----------------
// slot: 0:Wm1a 1:Wm1b 2:Wm2 3:Wp1 4:Ws1 5:Wn1a 6:Wn1b 7:Wn2
__global__ void transpose_weights_kernel(const float* __restrict__ Wm1,
                                         const float* __restrict__ Wm2,
                                         const float* __restrict__ Wp1,
                                         const float* __restrict__ Ws1,
                                         const float* __restrict__ Wn1,
                                         const float* __restrict__ Wn2) {
    int bid = blockIdx.x;           // 40 blocks
    int l = bid >> 3, slot = bid & 7;
    const float* src;
    switch (slot) {
        case 0: src = Wm1 + (size_t)l*260*128;           break;
        case 1: src = Wm1 + ((size_t)l*260 + 128)*128;   break;
        case 2: src = Wm2 + (size_t)l*128*128;           break;
        case 3: src = Wp1 + (size_t)l*128*128;           break;
        case 4: src = Ws1 + (size_t)l*128*128;           break;
        case 5: src = Wn1 + (size_t)l*256*128;           break;
        case 6: src = Wn1 + ((size_t)l*256 + 128)*128;   break;
        default:src = Wn2 + (size_t)l*128*128;           break;
    }
    float* dst = g_Wt + (size_t)bid*128*132;
    for (int o = threadIdx.x; o < 128*132; o += 256) {
        int c = o / 132, k = o - c*132;
        dst[o] = (k < 128) ? src[k*128 + c] : 0.0f;
    }
}

// ---------------- generic node GEMM (f32x2) ----------------
#define GEMM2_SMEM ((64*132 + 128*132)*4)
__global__ void __launch_bounds__(256)
gemm2_kernel(const float* __restrict__ A, const float* __restrict__ Wt,
             const float* __restrict__ bias, const float* __restrict__ Cin,
             float* __restrict__ C, int M, int act) {
    extern __shared__ float sm[];
    float* As = sm;              // 64*132
    float* Ws = sm + 64*132;     // 128*132
    int tid = threadIdx.x;
    int row0 = blockIdx.x * 64;

    for (int idx = tid; idx < 64*32; idx += 256) {
        int r = idx >> 5, c4 = (idx & 31) * 4;
        float4 v = make_float4(0.f, 0.f, 0.f, 0.f);
        if (row0 + r < M) v = *(const float4*)(A + (size_t)(row0 + r)*128 + c4);
        *(float4*)(As + r*132 + c4) = v;
    }
    for (int idx = tid; idx < 128*33; idx += 256)
        *(float4*)(Ws + idx*4) = *(const float4*)(Wt + (size_t)idx*4);
    __syncthreads();

    int tx = tid & 15, ty = tid >> 4;
    int r0 = ty * 4;
    u64 acc[4][8];
    mm2(As, Ws, r0, tx, acc);

    #pragma unroll
    for (int i = 0; i < 4; i++) {
        int r = row0 + r0 + i;
        if (r >= M) continue;
        #pragma unroll
        for (int j = 0; j < 8; j++) {
            int c = tx + 16*j;
            float v = pairsum(acc[i][j]);
            if (Cin)  v += Cin[(size_t)r*128 + c];
            if (bias) v += bias[c];
            if (act)  v = silu_f(v);
            C[(size_t)r*128 + c] = v;
        }
    }
}

// ---------------- init kernels ----------------
__global__ void node_init_kernel(const int* __restrict__ atoms, const float* __restrict__ emb) {
    int idx = blockIdx.x*256 + threadIdx.x;
    int i = idx >> 7, d = idx & 127;
    g_feat[idx] = emb[atoms[i]*128 + d];
}

__global__ void com_kernel(const int* __restrict__ batch) {
    int i = blockIdx.x*256 + threadIdx.x;
    if (i >= Nn) return;
    int b = batch[i];
    atomicAdd(&g_com[b*3+0], g_pos[i*3+0]);
    atomicAdd(&g_com[b*3+1], g_pos[i*3+1]);
    atomicAdd(&g_com[b*3+2], g_pos[i*3+2]);
    atomicAdd(&g_cnt[b], 1.0f);
}

__global__ void deg_kernel(const int* __restrict__ ei) {
    int e = blockIdx.x*256 + threadIdx.x;
    if (e >= Ee) return;
    atomicAdd(&g_deg[ei[e]], 1.0f);
}

__global__ void vocab_kernel(const float* __restrict__ emb, const float* __restrict__ Wsi1,
                             const float* __restrict__ WsiC1, const float* __restrict__ bsiC1,
                             const float* __restrict__ WsiC2, const float* __restrict__ bsiC2) {
    __shared__ float es[128];
    __shared__ float redv[128];
    int v = blockIdx.x, j = threadIdx.x;
    es[j] = emb[v*128 + j];
    __syncthreads();
    float p1 = 0.f, p2 = 0.f, hc = 0.f;
    for (int k = 0; k < 128; k++) {
        float e = es[k];
        p1 = fmaf(e, Wsi1[(1 + k)*128 + j], p1);
        p2 = fmaf(e, Wsi1[(129 + k)*128 + j], p2);
        hc = fmaf(e, WsiC1[k*128 + j], hc);
    }
    g_P1[v*128 + j] = p1;
    g_P2[v*128 + j] = p2;
    hc = silu_f(hc + bsiC1[j]);
    redv[j] = hc * WsiC2[j*3 + 2];
    __syncthreads();
    for (int s = 64; s > 0; s >>= 1) {
        if (j < s) redv[j] += redv[j + s];
        __syncthreads();
    }
    if (j == 0) g_cmsg[v] = redv[0] + bsiC2[2];
}

__global__ void edge_init_kernel(const int* __restrict__ ei, const int* __restrict__ atoms,
                                 const float* __restrict__ Wsi1, const float* __restrict__ bsi1,
                                 const float* __restrict__ Wsi2, const float* __restrict__ bsi2) {
    int e = blockIdx.x*8 + (threadIdx.x >> 5);
    int lane = threadIdx.x & 31;
    int r = ei[e], c = ei[Ee + e];
    float dp0 = g_pos[r*3+0] - g_pos[c*3+0];
    float dp1 = g_pos[r*3+1] - g_pos[c*3+1];
    float dp2 = g_pos[r*3+2] - g_pos[c*3+2];
    float dist = sqrtf(dp0*dp0 + dp1*dp1 + dp2*dp2);
    int ar = atoms[r], ac = atoms[c];
    float partial = 0.f;
    #pragma unroll
    for (int q = 0; q < 4; q++) {
        int d = lane + q*32;
        float h = silu_f(dist*Wsi1[d] + g_P1[ar*128 + d] + g_P2[ac*128 + d] + bsi1[d]);
        partial = fmaf(h, Wsi2[d*3 + 2], partial);
    }
    #pragma unroll
    for (int off = 16; off > 0; off >>= 1)
        partial += __shfl_xor_sync(0xffffffffu, partial, off);
    if (lane == 0) {
        float msg2 = partial + bsi2[2];
        float y2[5];
        sph2(dp0, dp1, dp2, y2);
        #pragma unroll
        for (int q = 0; q < 5; q++)
            atomicAdd(&g_ssum[r*9 + 4 + q], y2[q]*msg2);
    }
}

__global__ void sh_init_kernel(const int* __restrict__ atoms, const int* __restrict__ batch) {
    int i = blockIdx.x*256 + threadIdx.x;
    if (i >= Nn) return;
    float dg = fmaxf(g_deg[i], 1.0f);
    int b = batch[i];
    float cn = fmaxf(g_cnt[b], 1.0f);
    float vx = g_pos[i*3+0] - g_com[b*3+0]/cn;
    float vy = g_pos[i*3+1] - g_com[b*3+1]/cn;
    float vz = g_pos[i*3+2] - g_com[b*3+2]/cn;
    float y2[5];
    sph2(vx, vy, vz, y2);
    float cm = g_cmsg[atoms[i]];
    #pragma unroll
    for (int q = 0; q < 4; q++) g_sh[i*9 + q] = 0.0f;
    #pragma unroll
    for (int q = 0; q < 5; q++)
        g_sh[i*9 + 4 + q] = g_ssum[i*9 + 4 + q]/dg + cm*y2[q];
}

// ---------------- fused edge mega-kernel ----------------
// h = silu(featA[row]+featB[col]+scalar terms) -> m = silu(h@Wm2+bm2)
// -> pscal = silu(m@Wp1+bp1)@Wp2+bp2 ; svec = silu(m@Ws1+bs1)@Ws2+bs2 -> scatters
#define FE_SMEM_FLOATS (8448 + 8448 + 16896 + 3072 + 128 + 384 + 256 + 256 + 640)
#define FE_SMEM_BYTES  (FE_SMEM_FLOATS*4 + 128*4)
__global__ void __launch_bounds__(256)
fused_edge_kernel(const int* __restrict__ ei,
                  const float* __restrict__ Wt_m2, const float* __restrict__ bm2l,
                  const float* __restrict__ Wt_p1, const float* __restrict__ bp1l,
                  const float* __restrict__ Wp2l,  const float* __restrict__ bp2l,
                  const float* __restrict__ Wt_s1, const float* __restrict__ bs1l,
                  const float* __restrict__ Ws2l,  const float* __restrict__ bs2l,
                  const float* __restrict__ Wm1tail, const float* __restrict__ bm1l) {
    extern __shared__ float sm[];
    float* h_s  = sm;                 // 64*132
    float* m_s  = h_s  + 8448;        // 64*132
    float* Wt   = m_s  + 8448;        // 128*132
    float* red  = Wt   + 16896;       // 3*64*16
    float* bh   = red  + 3072;        // 128
    float* w2s  = bh   + 128;         // 384
    float* outs = w2s  + 384;         // 64*4
    float* scal = outs + 256;         // 64*4 (d2, ip0, ip1, ip2)
    float* wtl  = scal + 256;         // 5*128 (Wm1 tail rows + bm1)
    int*   ridx = (int*)(wtl + 640);  // 64
    int*   cidx = ridx + 64;          // 64

    int tid = threadIdx.x;
    int e0 = blockIdx.x * 64;

    // stage 0: indices + tail weights
    if (tid < 64) {
        ridx[tid] = ei[e0 + tid];
        cidx[tid] = ei[Ee + e0 + tid];
    }
    for (int idx = tid; idx < 640; idx += 256)
        wtl[idx] = (idx < 512) ? Wm1tail[idx] : bm1l[idx - 512];
    __syncthreads();

    // per-edge scalars
    if (tid < 64) {
        int r = ridx[tid], c = cidx[tid];
        float dp0 = g_pos[r*3+0] - g_pos[c*3+0];
        float dp1 = g_pos[r*3+1] - g_pos[c*3+1];
        float dp2 = g_pos[r*3+2] - g_pos[c*3+2];
        float d2 = dp0*dp0 + dp1*dp1 + dp2*dp2;
        float ip0 = g_sh[r*9+0]*g_sh[c*9+0];
        float ip1 = g_sh[r*9+1]*g_sh[c*9+1] + g_sh[r*9+2]*g_sh[c*9+2] + g_sh[r*9+3]*g_sh[c*9+3];
        float ip2 = 0.f;
        #pragma unroll
        for (int q = 4; q < 9; q++) ip2 += g_sh[r*9+q]*g_sh[c*9+q];
        scal[tid*4+0] = d2; scal[tid*4+1] = ip0; scal[tid*4+2] = ip1; scal[tid*4+3] = ip2;
    }
    __syncthreads();

    // stage 1: build h tile + load Wm2^T + bm2
    for (int idx = tid; idx < 64*32; idx += 256) {
        int e = idx >> 5, c4 = (idx & 31) * 4;
        int r = ridx[e], c = cidx[e];
        float4 fa = *(const float4*)(g_featA + (size_t)r*128 + c4);
        float4 fb = *(const float4*)(g_featB + (size_t)c*128 + c4);
        float d2 = scal[e*4+0], i0 = scal[e*4+1], i1 = scal[e*4+2], i2 = scal[e*4+3];
        float4 o;
        o.x = silu_f(fa.x + fb.x + d2*wtl[c4+0] + i0*wtl[128+c4+0] + i1*wtl[256+c4+0] + i2*wtl[384+c4+0] + wtl[512+c4+0]);
        o.y = silu_f(fa.y + fb.y + d2*wtl[c4+1] + i0*wtl[128+c4+1] + i1*wtl[256+c4+1] + i2*wtl[384+c4+1] + wtl[512+c4+1]);
        o.z = silu_f(fa.z + fb.z + d2*wtl[c4+2] + i0*wtl[128+c4+2] + i1*wtl[256+c4+2] + i2*wtl[384+c4+2] + wtl[512+c4+2]);
        o.w = silu_f(fa.w + fb.w + d2*wtl[c4+3] + i0*wtl[128+c4+3] + i1*wtl[256+c4+3] + i2*wtl[384+c4+3] + wtl[512+c4+3]);
        *(float4*)(h_s + e*132 + c4) = o;
    }
    for (int idx = tid; idx < 128*33; idx += 256)
        *(float4*)(Wt + idx*4) = *(const float4*)(Wt_m2 + idx*4);
    if (tid < 128) bh[tid] = bm2l[tid];
    __syncthreads();

    int tx = tid & 15, ty = tid >> 4;
    int r0 = ty * 4;

    // stage 2: m = silu(h @ Wm2 + bm2)
    {
        u64 acc[4][8];
        mm2(h_s, Wt, r0, tx, acc);
        #pragma unroll
        for (int i = 0; i < 4; i++)
            #pragma unroll
            for (int j = 0; j < 8; j++) {
                int c = tx + 16*j;
                m_s[(r0 + i)*132 + c] = silu_f(pairsum(acc[i][j]) + bh[c]);
            }
    }
    __syncthreads();

    // stage 3: pscal
    for (int idx = tid; idx < 128*33; idx += 256)
        *(float4*)(Wt + idx*4) = *(const float4*)(Wt_p1 + idx*4);
    if (tid < 128) { bh[tid] = bp1l[tid]; w2s[tid] = Wp2l[tid]; }
    __syncthreads();
    {
        u64 acc[4][8];
        mm2(m_s, Wt, r0, tx, acc);
        #pragma unroll
        for (int i = 0; i < 4; i++) {
            float part = 0.f;
            #pragma unroll
            for (int j = 0; j < 8; j++) {
                int c = tx + 16*j;
                part = fmaf(silu_f(pairsum(acc[i][j]) + bh[c]), w2s[c], part);
            }
            red[(r0 + i)*16 + tx] = part;
        }
    }
    __syncthreads();
    if (tid < 64) {
        float s = 0.f;
        #pragma unroll
        for (int x = 0; x < 16; x++) s += red[tid*16 + x];
        outs[tid*4 + 0] = s + bp2l[0];
    }
    // stage 4 fill (overlaps reduce; Wt reads done at previous sync)
    for (int idx = tid; idx < 128*33; idx += 256)
        *(float4*)(Wt + idx*4) = *(const float4*)(Wt_s1 + idx*4);
    if (tid < 128) {
        bh[tid] = bs1l[tid];
        w2s[tid*3+0] = Ws2l[tid*3+0];
        w2s[tid*3+1] = Ws2l[tid*3+1];
        w2s[tid*3+2] = Ws2l[tid*3+2];
    }
    __syncthreads();
    {
        u64 acc[4][8];
        mm2(m_s, Wt, r0, tx, acc);
        float part[4][3];
        #pragma unroll
        for (int i = 0; i < 4; i++) { part[i][0] = 0.f; part[i][1] = 0.f; part[i][2] = 0.f; }
        #pragma unroll
        for (int i = 0; i < 4; i++)
            #pragma unroll
            for (int j = 0; j < 8; j++) {
                int c = tx + 16*j;
                float hv = silu_f(pairsum(acc[i][j]) + bh[c]);
                part[i][0] = fmaf(hv, w2s[c*3+0], part[i][0]);
                part[i][1] = fmaf(hv, w2s[c*3+1], part[i][1]);
                part[i][2] = fmaf(hv, w2s[c*3+2], part[i][2]);
            }
        #pragma unroll
        for (int t = 0; t < 3; t++)
            #pragma unroll
            for (int i = 0; i < 4; i++)
                red[t*1024 + (r0 + i)*16 + tx] = part[i][t];
    }
    __syncthreads();

    // stage 5: reductions + all scatters
    if (tid < 64) {
        #pragma unroll
        for (int t = 0; t < 3; t++) {
            float s = 0.f;
            #pragma unroll
            for (int x = 0; x < 16; x++) s += red[t*1024 + tid*16 + x];
            outs[tid*4 + 1 + t] = s + bs2l[t];
        }
        int r = ridx[tid], c = cidx[tid];
        float psc = outs[tid*4 + 0];
        float s0 = outs[tid*4 + 1], s1 = outs[tid*4 + 2], s2 = outs[tid*4 + 3];
        float dp0 = g_pos[r*3+0] - g_pos[c*3+0];
        float dp1 = g_pos[r*3+1] - g_pos[c*3+1];
        float dp2 = g_pos[r*3+2] - g_pos[c*3+2];
        atomicAdd(&g_psum[r*3+0], dp0*psc);
        atomicAdd(&g_psum[r*3+1], dp1*psc);
        atomicAdd(&g_psum[r*3+2], dp2*psc);
        #pragma unroll
        for (int q = 0; q < 9; q++) {
            float diff = g_sh[r*9 + q] - g_sh[c*9 + q];
            float w = (q == 0) ? s0 : (q < 4) ? s1 : s2;
            atomicAdd(&g_ssum[r*9 + q], diff*w);
        }
    }
    {
        int ee = tid >> 2, part = tid & 3;
        int r = ridx[ee];
        #pragma unroll
        for (int d = part*32; d < part*32 + 32; d++)
            atomicAdd(&g_msum[(size_t)r*128 + d], m_s[ee*132 + d]);
    }
}

__global__ void divm_kernel() {
    int idx = blockIdx.x*256 + threadIdx.x;
    g_msum[idx] /= fmaxf(g_deg[idx >> 7], 1.0f);
}

__global__ void posh_kernel() {
    int i = blockIdx.x*256 + threadIdx.x;
    if (i >= Nn) return;
    float inv = 1.0f / fmaxf(g_deg[i], 1.0f);
    #pragma unroll
    for (int q = 0; q < 3; q++) g_pos[i*3 + q] += g_psum[i*3 + q]*inv;
    #pragma unroll
    for (int q = 0; q < 9; q++) g_sh[i*9 + q] += g_ssum[i*9 + q]*inv;
}

// ---------------- readout ----------------
__global__ void pool_kernel(const int* __restrict__ batch) {
    int idx = blockIdx.x*256 + threadIdx.x;
    if (idx >= Nn*140) return;
    int i = idx / 140, c = idx % 140;
    float v;
    if (c < 128)      v = g_feat[(size_t)i*128 + c];
    else if (c < 131) v = g_pos[i*3 + (c - 128)];
    else              v = g_sh[i*9 + (c - 131)];
    atomicAdd(&g_pool[batch[i]*140 + c], v);
}

__global__ void pred_kernel(const float* __restrict__ Wpred, const float* __restrict__ bpred,
                            float* __restrict__ out) {
    int g = blockIdx.x, lane = threadIdx.x;
    float s = 0.f;
    for (int c = lane; c < 140; c += 32)
        s = fmaf(g_pool[g*140 + c], Wpred[c], s);
    #pragma unroll
    for (int off = 16; off > 0; off >>= 1)
        s += __shfl_xor_sync(0xffffffffu, s, off);
    if (lane == 0) out[g] = s + bpred[0];
}

// ---------------- host ----------------
extern "C" void kernel_launch(void* const* d_in, const int* in_sizes, int n_in,
                              void* d_out, int out_size) {
    const int*   atoms = (const int*)d_in[0];
    const int*   ei    = (const int*)d_in[1];
    const int*   batch = (const int*)d_in[2];
    const float* pos   = (const float*)d_in[3];
    const float* emb   = (const float*)d_in[4];
    const float* Wsi1  = (const float*)d_in[5];  const float* bsi1  = (const float*)d_in[6];
    const float* Wsi2  = (const float*)d_in[7];  const float* bsi2  = (const float*)d_in[8];
    const float* WsiC1 = (const float*)d_in[9];  const float* bsiC1 = (const float*)d_in[10];
    const float* WsiC2 = (const float*)d_in[11]; const float* bsiC2 = (const float*)d_in[12];
    const float* Wm1   = (const float*)d_in[13]; const float* bm1   = (const float*)d_in[14];
    const float* Wm2   = (const float*)d_in[15]; const float* bm2   = (const float*)d_in[16];
    const float* Wp1   = (const float*)d_in[17]; const float* bp1   = (const float*)d_in[18];
    const float* Wp2   = (const float*)d_in[19]; const float* bp2   = (const float*)d_in[20];
    const float* Wn1   = (const float*)d_in[21]; const float* bn1   = (const float*)d_in[22];
    const float* Wn2   = (const float*)d_in[23]; const float* bn2   = (const float*)d_in[24];
    const float* Ws1   = (const float*)d_in[25]; const float* bs1   = (const float*)d_in[26];
    const float* Ws2   = (const float*)d_in[27]; const float* bs2   = (const float*)d_in[28];
    const float* Wpred = (const float*)d_in[29]; const float* bpred = (const float*)d_in[30];
    float* out = (float*)d_out;

    cudaFuncSetAttribute(gemm2_kernel, cudaFuncAttributeMaxDynamicSharedMemorySize, GEMM2_SMEM);
    cudaFuncSetAttribute(fused_edge_kernel, cudaFuncAttributeMaxDynamicSharedMemorySize, FE_SMEM_BYTES);

    void *p_msum, *p_psum, *p_ssum, *p_deg, *p_com, *p_cnt, *p_pool, *p_pos;
    void *p_feat, *p_featA, *p_featB, *p_tmp, *p_Wt;
    cudaGetSymbolAddress(&p_msum, g_msum);
    cudaGetSymbolAddress(&p_psum, g_psum);
    cudaGetSymbolAddress(&p_ssum, g_ssum);
    cudaGetSymbolAddress(&p_deg,  g_deg);
    cudaGetSymbolAddress(&p_com,  g_com);
    cudaGetSymbolAddress(&p_cnt,  g_cnt);
    cudaGetSymbolAddress(&p_pool, g_pool);
    cudaGetSymbolAddress(&p_pos,  g_pos);
    cudaGetSymbolAddress(&p_feat,  g_feat);
    cudaGetSymbolAddress(&p_featA, g_featA);
    cudaGetSymbolAddress(&p_featB, g_featB);
    cudaGetSymbolAddress(&p_tmp,   g_tmp);
    cudaGetSymbolAddress(&p_Wt,    g_Wt);
    const float* Wtb = (const float*)p_Wt;

    cudaMemsetAsync(p_deg,  0, Nn*4, 0);
    cudaMemsetAsync(p_com,  0, Gg*3*4, 0);
    cudaMemsetAsync(p_cnt,  0, Gg*4, 0);
    cudaMemsetAsync(p_ssum, 0, Nn*9*4, 0);
    cudaMemsetAsync(p_pool, 0, Gg*140*4, 0);
    cudaMemcpyAsync(p_pos, pos, Nn*3*4, cudaMemcpyDeviceToDevice, 0);

    transpose_weights_kernel<<<Ll*8, 256>>>(Wm1, Wm2, Wp1, Ws1, Wn1, Wn2);
    node_init_kernel<<<(Nn*128)/256, 256>>>(atoms, emb);
    com_kernel<<<(Nn + 255)/256, 256>>>(batch);
    deg_kernel<<<(Ee + 255)/256, 256>>>(ei);
    vocab_kernel<<<10, 128>>>(emb, Wsi1, WsiC1, bsiC1, WsiC2, bsiC2);
    edge_init_kernel<<<Ee/8, 256>>>(ei, atoms, Wsi1, bsi1, Wsi2, bsi2);
    sh_init_kernel<<<(Nn + 255)/256, 256>>>(atoms, batch);

    int gridN = (Nn + 63)/64;   // 157
    int gridE = Ee/64;          // 2500
    const size_t SLOT = 128*132;

    for (int l = 0; l < Ll; l++) {
        cudaMemsetAsync(p_msum, 0, (size_t)Nn*128*4, 0);
        cudaMemsetAsync(p_psum, 0, Nn*3*4, 0);
        cudaMemsetAsync(p_ssum, 0, Nn*9*4, 0);

        const float* Wl = Wtb + (size_t)l*8*SLOT;

        // node-level factorization of the edge-MLP input layer
        gemm2_kernel<<<gridN, 256, GEMM2_SMEM>>>(
            (const float*)p_feat, Wl + 0*SLOT, nullptr, nullptr, (float*)p_featA, Nn, 0);
        gemm2_kernel<<<gridN, 256, GEMM2_SMEM>>>(
            (const float*)p_feat, Wl + 1*SLOT, nullptr, nullptr, (float*)p_featB, Nn, 0);

        fused_edge_kernel<<<gridE, 256, FE_SMEM_BYTES>>>(
            ei,
            Wl + 2*SLOT, bm2 + l*128,
            Wl + 3*SLOT, bp1 + l*128, Wp2 + l*128, bp2 + l,
            Wl + 4*SLOT, bs1 + l*128, Ws2 + l*384, bs2 + l*3,
            Wm1 + ((size_t)l*260 + 256)*128, bm1 + l*128);

        divm_kernel<<<(Nn*128)/256, 256>>>();
        posh_kernel<<<(Nn + 255)/256, 256>>>();

        // node update MLP
        gemm2_kernel<<<gridN, 256, GEMM2_SMEM>>>(
            (const float*)p_feat, Wl + 5*SLOT, nullptr, nullptr, (float*)p_tmp, Nn, 0);
        gemm2_kernel<<<gridN, 256, GEMM2_SMEM>>>(
            (const float*)p_msum, Wl + 6*SLOT, bn1 + l*128,
            (const float*)p_tmp, (float*)p_tmp, Nn, 1);
        gemm2_kernel<<<gridN, 256, GEMM2_SMEM>>>(
            (const float*)p_tmp, Wl + 7*SLOT, bn2 + l*128, nullptr, (float*)p_feat, Nn, 0);
    }

    pool_kernel<<<(Nn*140 + 255)/256, 256>>>(batch);
    pred_kernel<<<Gg, 32>>>(Wpred, bpred, out);
}

// round 3
// speedup vs baseline: 1.4285x; 1.1724x over previous
#include <cuda_runtime.h>
#include <math.h>

#define Nn 10000
#define Ee 160000
#define Gg 100
#define Ll 5

typedef unsigned long long u64;

// ---------------- scratch (device globals: no allocation allowed) ----------------
__device__ float g_feat [Nn*128];
__device__ float g_featA[Nn*128];
__device__ float g_featB[Nn*128];
__device__ float g_tmp  [Nn*128];
__device__ float g_sh   [Nn*9];
__device__ float g_pos  [Nn*3];
__device__ float g_msum [Nn*128];
__device__ float g_psum [Nn*3];
__device__ float g_ssum [Nn*9];
__device__ float g_deg  [Nn];
__device__ float g_com  [Gg*3];
__device__ float g_cnt  [Gg];
__device__ float g_P1   [10*128];
__device__ float g_P2   [10*128];
__device__ float g_cmsg [10];
__device__ float g_pool [Gg*140];
// padded weights: 5 layers x 8 slots x [128 k][132 cols (128 + pad)]
__device__ float g_Wt   [Ll*8*128*132];

__device__ __forceinline__ float silu_f(float x) { return x / (1.0f + __expf(-x)); }

__device__ __forceinline__ void sph2(float vx, float vy, float vz, float* o) {
    const float S3  = 1.7320508075688772f;
    const float HS3 = 0.8660254037844386f;
    float r = sqrtf(vx*vx + vy*vy + vz*vz);
    float inv = 1.0f / fmaxf(r, 1e-12f);
    float x = vx*inv, y = vy*inv, z = vz*inv;
    o[0] = S3*x*z;
    o[1] = S3*x*y;
    o[2] = y*y - 0.5f*(x*x + z*z);
    o[3] = S3*y*z;
    o[4] = HS3*(z*z - x*x);
}

// ---------------- packed f32x2 primitives ----------------
__device__ __forceinline__ u64 fma2(u64 a, u64 b, u64 c) {
    u64 d;
    asm("fma.rn.f32x2 %0, %1, %2, %3;" : "=l"(d) : "l"(a), "l"(b), "l"(c));
    return d;
}
__device__ __forceinline__ u64 pk2(float x) {
    u64 d;
    asm("mov.b64 %0, {%1, %1};" : "=l"(d) : "r"(__float_as_uint(x)));
    return d;
}
__device__ __forceinline__ float2 up2(u64 v) {
    float2 f;
    asm("mov.b64 {%0, %1}, %2;" : "=f"(f.x), "=f"(f.y) : "l"(v));
    return f;
}

// ---------------- col-packed GEMM core ----------------
// As: [128 rows][132] row-major fp32.  Ws: [128 k][132] row-major (natural [k][c]).
// Thread (tx=tid&15, ty=tid>>4): rows r0=ty*8..+7, cols c0=tx*8..+7.
// acc[i][j]: u64 packing cols {c0+2j, c0+2j+1} for row r0+i.
__device__ __forceinline__ void mm_cp(const float* __restrict__ As,
                                      const float* __restrict__ Ws,
                                      int r0, int c0, u64 acc[8][4]) {
    #pragma unroll
    for (int i = 0; i < 8; i++)
        #pragma unroll
        for (int j = 0; j < 4; j++) acc[i][j] = 0ull;

    const float* ap = As + r0*132;
    const float* wp = Ws + c0;

    #pragma unroll 2
    for (int k0 = 0; k0 < 128; k0 += 2) {
        float2 a2[8];
        #pragma unroll
        for (int i = 0; i < 8; i++)
            a2[i] = *(const float2*)(ap + i*132 + k0);
        const float* w0 = wp + k0*132;
        ulonglong2 p0 = *(const ulonglong2*)(w0);
        ulonglong2 p1 = *(const ulonglong2*)(w0 + 4);
        ulonglong2 q0 = *(const ulonglong2*)(w0 + 132);
        ulonglong2 q1 = *(const ulonglong2*)(w0 + 136);
        #pragma unroll
        for (int i = 0; i < 8; i++) {
            u64 ax = pk2(a2[i].x);
            acc[i][0] = fma2(ax, p0.x, acc[i][0]);
            acc[i][1] = fma2(ax, p0.y, acc[i][1]);
            acc[i][2] = fma2(ax, p1.x, acc[i][2]);
            acc[i][3] = fma2(ax, p1.y, acc[i][3]);
        }
        #pragma unroll
        for (int i = 0; i < 8; i++) {
            u64 ay = pk2(a2[i].y);
            acc[i][0] = fma2(ay, q0.x, acc[i][0]);
            acc[i][1] = fma2(ay, q0.y, acc[i][1]);
            acc[i][2] = fma2(ay, q1.x, acc[i][2]);
            acc[i][3] = fma2(ay, q1.y, acc[i][3]);
        }
    }
}

// ---------------- weight pad-copy (once per launch) ----------------
// slot: 0:Wm1a 1:Wm1b 2:Wm2 3:Wp1 4:Ws1 5:Wn1a 6:Wn1b 7:Wn2  (all natural k-major)
__global__ void pad_weights_kernel(const float* __restrict__ Wm1,
                                   const float* __restrict__ Wm2,
                                   const float* __restrict__ Wp1,
                                   const float* __restrict__ Ws1,
                                   const float* __restrict__ Wn1,
                                   const float* __restrict__ Wn2) {
    int bid = blockIdx.x;           // 40 blocks
    int l = bid >> 3, slot = bid & 7;
    const float* src;
    switch (slot) {
        case 0: src = Wm1 + (size_t)l*260*128;           break;
        case 1: src = Wm1 + ((size_t)l*260 + 128)*128;   break;
        case 2: src = Wm2 + (size_t)l*128*128;           break;
        case 3: src = Wp1 + (size_t)l*128*128;           break;
        case 4: src = Ws1 + (size_t)l*128*128;           break;
        case 5: src = Wn1 + (size_t)l*256*128;           break;
        case 6: src = Wn1 + ((size_t)l*256 + 128)*128;   break;
        default:src = Wn2 + (size_t)l*128*128;           break;
    }
    float* dst = g_Wt + (size_t)bid*128*132;
    for (int o = threadIdx.x; o < 128*132; o += 256) {
        int k = o / 132, c = o - k*132;
        dst[o] = (c < 128) ? src[k*128 + c] : 0.0f;
    }
}

// ---------------- generic node GEMM (col-packed, 128-row tiles) ----------------
#define GEMM2_SMEM (2*128*132*4)
__global__ void __launch_bounds__(256)
gemm2_kernel(const float* __restrict__ A, const float* __restrict__ Wk,
             const float* __restrict__ bias, const float* __restrict__ Cin,
             float* __restrict__ C, int M, int act) {
    extern __shared__ float sm[];
    float* As = sm;               // 128*132
    float* Ws = sm + 128*132;     // 128*132
    int tid = threadIdx.x;
    int row0 = blockIdx.x * 128;

    for (int idx = tid; idx < 128*32; idx += 256) {
        int r = idx >> 5, c4 = (idx & 31) * 4;
        float4 v = make_float4(0.f, 0.f, 0.f, 0.f);
        if (row0 + r < M) v = *(const float4*)(A + (size_t)(row0 + r)*128 + c4);
        *(float4*)(As + r*132 + c4) = v;
    }
    for (int idx = tid; idx < 128*33; idx += 256)
        *(float4*)(Ws + idx*4) = *(const float4*)(Wk + (size_t)idx*4);
    __syncthreads();

    int tx = tid & 15, ty = tid >> 4;
    int r0 = ty * 8, c0 = tx * 8;
    u64 acc[8][4];
    mm_cp(As, Ws, r0, c0, acc);

    #pragma unroll
    for (int i = 0; i < 8; i++) {
        int r = row0 + r0 + i;
        if (r >= M) continue;
        #pragma unroll
        for (int j = 0; j < 4; j++) {
            float2 f = up2(acc[i][j]);
            int c = c0 + 2*j;
            float v0 = f.x, v1 = f.y;
            if (Cin) {
                v0 += Cin[(size_t)r*128 + c];
                v1 += Cin[(size_t)r*128 + c + 1];
            }
            if (bias) { v0 += bias[c]; v1 += bias[c+1]; }
            if (act)  { v0 = silu_f(v0); v1 = silu_f(v1); }
            C[(size_t)r*128 + c]     = v0;
            C[(size_t)r*128 + c + 1] = v1;
        }
    }
}

// ---------------- init kernels ----------------
__global__ void node_init_kernel(const int* __restrict__ atoms, const float* __restrict__ emb) {
    int idx = blockIdx.x*256 + threadIdx.x;
    int i = idx >> 7, d = idx & 127;
    g_feat[idx] = emb[atoms[i]*128 + d];
}

__global__ void com_kernel(const int* __restrict__ batch) {
    int i = blockIdx.x*256 + threadIdx.x;
    if (i >= Nn) return;
    int b = batch[i];
    atomicAdd(&g_com[b*3+0], g_pos[i*3+0]);
    atomicAdd(&g_com[b*3+1], g_pos[i*3+1]);
    atomicAdd(&g_com[b*3+2], g_pos[i*3+2]);
    atomicAdd(&g_cnt[b], 1.0f);
}

__global__ void deg_kernel(const int* __restrict__ ei) {
    int e = blockIdx.x*256 + threadIdx.x;
    if (e >= Ee) return;
    atomicAdd(&g_deg[ei[e]], 1.0f);
}

__global__ void vocab_kernel(const float* __restrict__ emb, const float* __restrict__ Wsi1,
                             const float* __restrict__ WsiC1, const float* __restrict__ bsiC1,
                             const float* __restrict__ WsiC2, const float* __restrict__ bsiC2) {
    __shared__ float es[128];
    __shared__ float redv[128];
    int v = blockIdx.x, j = threadIdx.x;
    es[j] = emb[v*128 + j];
    __syncthreads();
    float p1 = 0.f, p2 = 0.f, hc = 0.f;
    for (int k = 0; k < 128; k++) {
        float e = es[k];
        p1 = fmaf(e, Wsi1[(1 + k)*128 + j], p1);
        p2 = fmaf(e, Wsi1[(129 + k)*128 + j], p2);
        hc = fmaf(e, WsiC1[k*128 + j], hc);
    }
    g_P1[v*128 + j] = p1;
    g_P2[v*128 + j] = p2;
    hc = silu_f(hc + bsiC1[j]);
    redv[j] = hc * WsiC2[j*3 + 2];
    __syncthreads();
    for (int s = 64; s > 0; s >>= 1) {
        if (j < s) redv[j] += redv[j + s];
        __syncthreads();
    }
    if (j == 0) g_cmsg[v] = redv[0] + bsiC2[2];
}

__global__ void edge_init_kernel(const int* __restrict__ ei, const int* __restrict__ atoms,
                                 const float* __restrict__ Wsi1, const float* __restrict__ bsi1,
                                 const float* __restrict__ Wsi2, const float* __restrict__ bsi2) {
    int e = blockIdx.x*8 + (threadIdx.x >> 5);
    int lane = threadIdx.x & 31;
    int r = ei[e], c = ei[Ee + e];
    float dp0 = g_pos[r*3+0] - g_pos[c*3+0];
    float dp1 = g_pos[r*3+1] - g_pos[c*3+1];
    float dp2 = g_pos[r*3+2] - g_pos[c*3+2];
    float dist = sqrtf(dp0*dp0 + dp1*dp1 + dp2*dp2);
    int ar = atoms[r], ac = atoms[c];
    float partial = 0.f;
    #pragma unroll
    for (int q = 0; q < 4; q++) {
        int d = lane + q*32;
        float h = silu_f(dist*Wsi1[d] + g_P1[ar*128 + d] + g_P2[ac*128 + d] + bsi1[d]);
        partial = fmaf(h, Wsi2[d*3 + 2], partial);
    }
    #pragma unroll
    for (int off = 16; off > 0; off >>= 1)
        partial += __shfl_xor_sync(0xffffffffu, partial, off);
    if (lane == 0) {
        float msg2 = partial + bsi2[2];
        float y2[5];
        sph2(dp0, dp1, dp2, y2);
        #pragma unroll
        for (int q = 0; q < 5; q++)
            atomicAdd(&g_ssum[r*9 + 4 + q], y2[q]*msg2);
    }
}

__global__ void sh_init_kernel(const int* __restrict__ atoms, const int* __restrict__ batch) {
    int i = blockIdx.x*256 + threadIdx.x;
    if (i >= Nn) return;
    float dg = fmaxf(g_deg[i], 1.0f);
    int b = batch[i];
    float cn = fmaxf(g_cnt[b], 1.0f);
    float vx = g_pos[i*3+0] - g_com[b*3+0]/cn;
    float vy = g_pos[i*3+1] - g_com[b*3+1]/cn;
    float vz = g_pos[i*3+2] - g_com[b*3+2]/cn;
    float y2[5];
    sph2(vx, vy, vz, y2);
    float cm = g_cmsg[atoms[i]];
    #pragma unroll
    for (int q = 0; q < 4; q++) g_sh[i*9 + q] = 0.0f;
    #pragma unroll
    for (int q = 0; q < 5; q++)
        g_sh[i*9 + 4 + q] = g_ssum[i*9 + 4 + q]/dg + cm*y2[q];
}

// ---------------- fused edge mega-kernel (128 edges / block) ----------------
#define FE_SMEM_BYTES ((3*16896 + 128 + 384 + 512 + 512 + 640 + 256)*4)
__global__ void __launch_bounds__(256)
fused_edge_kernel(const int* __restrict__ ei,
                  const float* __restrict__ Wk_m2, const float* __restrict__ bm2l,
                  const float* __restrict__ Wk_p1, const float* __restrict__ bp1l,
                  const float* __restrict__ Wp2l,  const float* __restrict__ bp2l,
                  const float* __restrict__ Wk_s1, const float* __restrict__ bs1l,
                  const float* __restrict__ Ws2l,  const float* __restrict__ bs2l,
                  const float* __restrict__ Wm1tail, const float* __restrict__ bm1l) {
    extern __shared__ float sm[];
    float* h_s  = sm;                  // 128*132
    float* m_s  = h_s + 16896;         // 128*132
    float* Wt   = m_s + 16896;         // 128*132
    float* red  = h_s;                 // alias (h dead after m-GEMM)
    float* bh   = Wt   + 16896;        // 128
    float* w2s  = bh   + 128;          // 384
    float* outs = w2s  + 384;          // 128*4
    float* scal = outs + 512;          // 128*4
    float* wtl  = scal + 512;          // 640
    int*   ridx = (int*)(wtl + 640);   // 128
    int*   cidx = ridx + 128;          // 128

    int tid = threadIdx.x;
    int e0 = blockIdx.x * 128;

    // stage 0: indices + per-edge scalars + tail weights + Wm2 fill
    if (tid < 128) {
        int r = ei[e0 + tid], c = ei[Ee + e0 + tid];
        ridx[tid] = r; cidx[tid] = c;
        float dp0 = g_pos[r*3+0] - g_pos[c*3+0];
        float dp1 = g_pos[r*3+1] - g_pos[c*3+1];
        float dp2 = g_pos[r*3+2] - g_pos[c*3+2];
        float d2 = dp0*dp0 + dp1*dp1 + dp2*dp2;
        float ip0 = g_sh[r*9+0]*g_sh[c*9+0];
        float ip1 = g_sh[r*9+1]*g_sh[c*9+1] + g_sh[r*9+2]*g_sh[c*9+2] + g_sh[r*9+3]*g_sh[c*9+3];
        float ip2 = 0.f;
        #pragma unroll
        for (int q = 4; q < 9; q++) ip2 += g_sh[r*9+q]*g_sh[c*9+q];
        scal[tid*4+0] = d2; scal[tid*4+1] = ip0; scal[tid*4+2] = ip1; scal[tid*4+3] = ip2;
    }
    for (int idx = tid; idx < 640; idx += 256)
        wtl[idx] = (idx < 512) ? Wm1tail[idx] : bm1l[idx - 512];
    for (int idx = tid; idx < 128*33; idx += 256)
        *(float4*)(Wt + idx*4) = *(const float4*)(Wk_m2 + idx*4);
    if (tid < 128) bh[tid] = bm2l[tid];
    __syncthreads();

    // stage 1: build h tile (gather featA/featB)
    for (int idx = tid; idx < 128*32; idx += 256) {
        int e = idx >> 5, c4 = (idx & 31) * 4;
        int r = ridx[e], c = cidx[e];
        float4 fa = *(const float4*)(g_featA + (size_t)r*128 + c4);
        float4 fb = *(const float4*)(g_featB + (size_t)c*128 + c4);
        float d2 = scal[e*4+0], i0 = scal[e*4+1], i1 = scal[e*4+2], i2 = scal[e*4+3];
        float4 o;
        o.x = silu_f(fa.x + fb.x + d2*wtl[c4+0] + i0*wtl[128+c4+0] + i1*wtl[256+c4+0] + i2*wtl[384+c4+0] + wtl[512+c4+0]);
        o.y = silu_f(fa.y + fb.y + d2*wtl[c4+1] + i0*wtl[128+c4+1] + i1*wtl[256+c4+1] + i2*wtl[384+c4+1] + wtl[512+c4+1]);
        o.z = silu_f(fa.z + fb.z + d2*wtl[c4+2] + i0*wtl[128+c4+2] + i1*wtl[256+c4+2] + i2*wtl[384+c4+2] + wtl[512+c4+2]);
        o.w = silu_f(fa.w + fb.w + d2*wtl[c4+3] + i0*wtl[128+c4+3] + i1*wtl[256+c4+3] + i2*wtl[384+c4+3] + wtl[512+c4+3]);
        *(float4*)(h_s + e*132 + c4) = o;
    }
    __syncthreads();

    int tx = tid & 15, ty = tid >> 4;
    int r0 = ty * 8, c0 = tx * 8;

    // stage 2: m = silu(h @ Wm2 + bm2)
    {
        u64 acc[8][4];
        mm_cp(h_s, Wt, r0, c0, acc);
        #pragma unroll
        for (int i = 0; i < 8; i++)
            #pragma unroll
            for (int j = 0; j < 4; j++) {
                float2 f = up2(acc[i][j]);
                int c = c0 + 2*j;
                m_s[(r0 + i)*132 + c]     = silu_f(f.x + bh[c]);
                m_s[(r0 + i)*132 + c + 1] = silu_f(f.y + bh[c+1]);
            }
    }
    __syncthreads();

    // stage 3 setup: Wp1/bp1/Wp2
    for (int idx = tid; idx < 128*33; idx += 256)
        *(float4*)(Wt + idx*4) = *(const float4*)(Wk_p1 + idx*4);
    if (tid < 128) { bh[tid] = bp1l[tid]; w2s[tid] = Wp2l[tid]; }
    __syncthreads();

    // stage 3: pscal partials -> red (h_s alias)
    {
        u64 acc[8][4];
        mm_cp(m_s, Wt, r0, c0, acc);
        #pragma unroll
        for (int i = 0; i < 8; i++) {
            float part = 0.f;
            #pragma unroll
            for (int j = 0; j < 4; j++) {
                float2 f = up2(acc[i][j]);
                int c = c0 + 2*j;
                part = fmaf(silu_f(f.x + bh[c]),   w2s[c],   part);
                part = fmaf(silu_f(f.y + bh[c+1]), w2s[c+1], part);
            }
            red[(r0 + i)*16 + tx] = part;
        }
    }
    __syncthreads();

    // stage 4 setup + p reduce
    if (tid < 128) {
        float s = 0.f;
        #pragma unroll
        for (int x = 0; x < 16; x++) s += red[tid*16 + x];
        outs[tid*4 + 0] = s + bp2l[0];
    }
    for (int idx = tid; idx < 128*33; idx += 256)
        *(float4*)(Wt + idx*4) = *(const float4*)(Wk_s1 + idx*4);
    if (tid < 128) {
        bh[tid] = bs1l[tid];
        w2s[tid*3+0] = Ws2l[tid*3+0];
        w2s[tid*3+1] = Ws2l[tid*3+1];
        w2s[tid*3+2] = Ws2l[tid*3+2];
    }
    __syncthreads();

    // stage 4: s partials (3 channels) -> red
    {
        u64 acc[8][4];
        mm_cp(m_s, Wt, r0, c0, acc);
        float part[8][3];
        #pragma unroll
        for (int i = 0; i < 8; i++) { part[i][0]=0.f; part[i][1]=0.f; part[i][2]=0.f; }
        #pragma unroll
        for (int i = 0; i < 8; i++)
            #pragma unroll
            for (int j = 0; j < 4; j++) {
                float2 f = up2(acc[i][j]);
                int c = c0 + 2*j;
                float h0 = silu_f(f.x + bh[c]);
                float h1 = silu_f(f.y + bh[c+1]);
                part[i][0] = fmaf(h0, w2s[c*3+0], fmaf(h1, w2s[(c+1)*3+0], part[i][0]));
                part[i][1] = fmaf(h0, w2s[c*3+1], fmaf(h1, w2s[(c+1)*3+1], part[i][1]));
                part[i][2] = fmaf(h0, w2s[c*3+2], fmaf(h1, w2s[(c+1)*3+2], part[i][2]));
            }
        #pragma unroll
        for (int t = 0; t < 3; t++)
            #pragma unroll
            for (int i = 0; i < 8; i++)
                red[t*2048 + (r0 + i)*16 + tx] = part[i][t];
    }
    __syncthreads();

    // stage 5: s reduce + p/s scatter (128 threads) ; msum scatter (all 256)
    if (tid < 128) {
        float sv[3];
        #pragma unroll
        for (int t = 0; t < 3; t++) {
            float s = 0.f;
            #pragma unroll
            for (int x = 0; x < 16; x++) s += red[t*2048 + tid*16 + x];
            sv[t] = s + bs2l[t];
        }
        int r = ridx[tid], c = cidx[tid];
        float psc = outs[tid*4 + 0];
        float dp0 = g_pos[r*3+0] - g_pos[c*3+0];
        float dp1 = g_pos[r*3+1] - g_pos[c*3+1];
        float dp2 = g_pos[r*3+2] - g_pos[c*3+2];
        atomicAdd(&g_psum[r*3+0], dp0*psc);
        atomicAdd(&g_psum[r*3+1], dp1*psc);
        atomicAdd(&g_psum[r*3+2], dp2*psc);
        #pragma unroll
        for (int q = 0; q < 9; q++) {
            float diff = g_sh[r*9 + q] - g_sh[c*9 + q];
            float w = (q == 0) ? sv[0] : (q < 4) ? sv[1] : sv[2];
            atomicAdd(&g_ssum[r*9 + q], diff*w);
        }
    }
    {
        int e = tid >> 1, half = tid & 1;
        int r = ridx[e];
        const float* src = m_s + e*132 + half*64;
        float* dst = g_msum + (size_t)r*128 + half*64;
        #pragma unroll
        for (int d = 0; d < 64; d += 4) {
            float4 v = *(const float4*)(src + d);
            asm volatile("red.global.add.v4.f32 [%0], {%1, %2, %3, %4};"
                         :: "l"(dst + d), "f"(v.x), "f"(v.y), "f"(v.z), "f"(v.w)
                         : "memory");
        }
    }
}

__global__ void divm_kernel() {
    int idx = blockIdx.x*256 + threadIdx.x;
    g_msum[idx] /= fmaxf(g_deg[idx >> 7], 1.0f);
}

__global__ void posh_kernel() {
    int i = blockIdx.x*256 + threadIdx.x;
    if (i >= Nn) return;
    float inv = 1.0f / fmaxf(g_deg[i], 1.0f);
    #pragma unroll
    for (int q = 0; q < 3; q++) g_pos[i*3 + q] += g_psum[i*3 + q]*inv;
    #pragma unroll
    for (int q = 0; q < 9; q++) g_sh[i*9 + q] += g_ssum[i*9 + q]*inv;
}

// ---------------- readout ----------------
__global__ void pool_kernel(const int* __restrict__ batch) {
    int idx = blockIdx.x*256 + threadIdx.x;
    if (idx >= Nn*140) return;
    int i = idx / 140, c = idx % 140;
    float v;
    if (c < 128)      v = g_feat[(size_t)i*128 + c];
    else if (c < 131) v = g_pos[i*3 + (c - 128)];
    else              v = g_sh[i*9 + (c - 131)];
    atomicAdd(&g_pool[batch[i]*140 + c], v);
}

__global__ void pred_kernel(const float* __restrict__ Wpred, const float* __restrict__ bpred,
                            float* __restrict__ out) {
    int g = blockIdx.x, lane = threadIdx.x;
    float s = 0.f;
    for (int c = lane; c < 140; c += 32)
        s = fmaf(g_pool[g*140 + c], Wpred[c], s);
    #pragma unroll
    for (int off = 16; off > 0; off >>= 1)
        s += __shfl_xor_sync(0xffffffffu, s, off);
    if (lane == 0) out[g] = s + bpred[0];
}

// ---------------- host ----------------
extern "C" void kernel_launch(void* const* d_in, const int* in_sizes, int n_in,
                              void* d_out, int out_size) {
    const int*   atoms = (const int*)d_in[0];
    const int*   ei    = (const int*)d_in[1];
    const int*   batch = (const int*)d_in[2];
    const float* pos   = (const float*)d_in[3];
    const float* emb   = (const float*)d_in[4];
    const float* Wsi1  = (const float*)d_in[5];  const float* bsi1  = (const float*)d_in[6];
    const float* Wsi2  = (const float*)d_in[7];  const float* bsi2  = (const float*)d_in[8];
    const float* WsiC1 = (const float*)d_in[9];  const float* bsiC1 = (const float*)d_in[10];
    const float* WsiC2 = (const float*)d_in[11]; const float* bsiC2 = (const float*)d_in[12];
    const float* Wm1   = (const float*)d_in[13]; const float* bm1   = (const float*)d_in[14];
    const float* Wm2   = (const float*)d_in[15]; const float* bm2   = (const float*)d_in[16];
    const float* Wp1   = (const float*)d_in[17]; const float* bp1   = (const float*)d_in[18];
    const float* Wp2   = (const float*)d_in[19]; const float* bp2   = (const float*)d_in[20];
    const float* Wn1   = (const float*)d_in[21]; const float* bn1   = (const float*)d_in[22];
    const float* Wn2   = (const float*)d_in[23]; const float* bn2   = (const float*)d_in[24];
    const float* Ws1   = (const float*)d_in[25]; const float* bs1   = (const float*)d_in[26];
    const float* Ws2   = (const float*)d_in[27]; const float* bs2   = (const float*)d_in[28];
    const float* Wpred = (const float*)d_in[29]; const float* bpred = (const float*)d_in[30];
    float* out = (float*)d_out;

    cudaFuncSetAttribute(gemm2_kernel, cudaFuncAttributeMaxDynamicSharedMemorySize, GEMM2_SMEM);
    cudaFuncSetAttribute(fused_edge_kernel, cudaFuncAttributeMaxDynamicSharedMemorySize, FE_SMEM_BYTES);

    void *p_msum, *p_psum, *p_ssum, *p_deg, *p_com, *p_cnt, *p_pool, *p_pos;
    void *p_feat, *p_featA, *p_featB, *p_tmp, *p_Wt;
    cudaGetSymbolAddress(&p_msum, g_msum);
    cudaGetSymbolAddress(&p_psum, g_psum);
    cudaGetSymbolAddress(&p_ssum, g_ssum);
    cudaGetSymbolAddress(&p_deg,  g_deg);
    cudaGetSymbolAddress(&p_com,  g_com);
    cudaGetSymbolAddress(&p_cnt,  g_cnt);
    cudaGetSymbolAddress(&p_pool, g_pool);
    cudaGetSymbolAddress(&p_pos,  g_pos);
    cudaGetSymbolAddress(&p_feat,  g_feat);
    cudaGetSymbolAddress(&p_featA, g_featA);
    cudaGetSymbolAddress(&p_featB, g_featB);
    cudaGetSymbolAddress(&p_tmp,   g_tmp);
    cudaGetSymbolAddress(&p_Wt,    g_Wt);
    const float* Wtb = (const float*)p_Wt;

    cudaMemsetAsync(p_deg,  0, Nn*4, 0);
    cudaMemsetAsync(p_com,  0, Gg*3*4, 0);
    cudaMemsetAsync(p_cnt,  0, Gg*4, 0);
    cudaMemsetAsync(p_ssum, 0, Nn*9*4, 0);
    cudaMemsetAsync(p_pool, 0, Gg*140*4, 0);
    cudaMemcpyAsync(p_pos, pos, Nn*3*4, cudaMemcpyDeviceToDevice, 0);

    pad_weights_kernel<<<Ll*8, 256>>>(Wm1, Wm2, Wp1, Ws1, Wn1, Wn2);
    node_init_kernel<<<(Nn*128)/256, 256>>>(atoms, emb);
    com_kernel<<<(Nn + 255)/256, 256>>>(batch);
    deg_kernel<<<(Ee + 255)/256, 256>>>(ei);
    vocab_kernel<<<10, 128>>>(emb, Wsi1, WsiC1, bsiC1, WsiC2, bsiC2);
    edge_init_kernel<<<Ee/8, 256>>>(ei, atoms, Wsi1, bsi1, Wsi2, bsi2);
    sh_init_kernel<<<(Nn + 255)/256, 256>>>(atoms, batch);

    int gridN = (Nn + 127)/128;  // 79
    int gridE = Ee/128;          // 1250
    const size_t SLOT = 128*132;

    for (int l = 0; l < Ll; l++) {
        cudaMemsetAsync(p_msum, 0, (size_t)Nn*128*4, 0);
        cudaMemsetAsync(p_psum, 0, Nn*3*4, 0);
        cudaMemsetAsync(p_ssum, 0, Nn*9*4, 0);

        const float* Wl = Wtb + (size_t)l*8*SLOT;

        // node-level factorization of the edge-MLP input layer
        gemm2_kernel<<<gridN, 256, GEMM2_SMEM>>>(
            (const float*)p_feat, Wl + 0*SLOT, nullptr, nullptr, (float*)p_featA, Nn, 0);
        gemm2_kernel<<<gridN, 256, GEMM2_SMEM>>>(
            (const float*)p_feat, Wl + 1*SLOT, nullptr, nullptr, (float*)p_featB, Nn, 0);

        fused_edge_kernel<<<gridE, 256, FE_SMEM_BYTES>>>(
            ei,
            Wl + 2*SLOT, bm2 + l*128,
            Wl + 3*SLOT, bp1 + l*128, Wp2 + l*128, bp2 + l,
            Wl + 4*SLOT, bs1 + l*128, Ws2 + l*384, bs2 + l*3,
            Wm1 + ((size_t)l*260 + 256)*128, bm1 + l*128);

        divm_kernel<<<(Nn*128)/256, 256>>>();
        posh_kernel<<<(Nn + 255)/256, 256>>>();

        // node update MLP
        gemm2_kernel<<<gridN, 256, GEMM2_SMEM>>>(
            (const float*)p_feat, Wl + 5*SLOT, nullptr, nullptr, (float*)p_tmp, Nn, 0);
        gemm2_kernel<<<gridN, 256, GEMM2_SMEM>>>(
            (const float*)p_msum, Wl + 6*SLOT, bn1 + l*128,
            (const float*)p_tmp, (float*)p_tmp, Nn, 1);
        gemm2_kernel<<<gridN, 256, GEMM2_SMEM>>>(
            (const float*)p_tmp, Wl + 7*SLOT, bn2 + l*128, nullptr, (float*)p_feat, Nn, 0);
    }

    pool_kernel<<<(Nn*140 + 255)/256, 256>>>(batch);
    pred_kernel<<<Gg, 32>>>(Wpred, bpred, out);
}

// round 4
// speedup vs baseline: 1.6407x; 1.1485x over previous
#include <cuda_runtime.h>
#include <math.h>

#define Nn 10000
#define Ee 160000
#define Gg 100
#define Ll 5
#define NTILES 2500

typedef unsigned long long u64;

// ---------------- scratch (device globals) ----------------
__device__ float g_feat [Nn*128];
__device__ float g_featA[Nn*128];
__device__ float g_featB[Nn*128];
__device__ float g_tmp  [Nn*128];
__device__ float g_sh   [Nn*9];
__device__ float g_pos  [Nn*3];
__device__ float g_msum [Nn*128];
__device__ float g_psum [Nn*3];
__device__ float g_ssum [Nn*9];
__device__ float g_deg  [Nn];
__device__ float g_com  [Gg*3];
__device__ float g_cnt  [Gg];
__device__ float g_P1   [10*128];
__device__ float g_P2   [10*128];
__device__ float g_cmsg [10];
__device__ float g_pool [Gg*140];
__device__ float g_m    [(size_t)Ee*128];
// padded weights: 5 layers x 8 slots x [128 k][132 cols]
__device__ float g_Wt   [Ll*8*128*132];

__device__ __forceinline__ float silu_f(float x) { return x / (1.0f + __expf(-x)); }

__device__ __forceinline__ void sph2(float vx, float vy, float vz, float* o) {
    const float S3  = 1.7320508075688772f;
    const float HS3 = 0.8660254037844386f;
    float r = sqrtf(vx*vx + vy*vy + vz*vz);
    float inv = 1.0f / fmaxf(r, 1e-12f);
    float x = vx*inv, y = vy*inv, z = vz*inv;
    o[0] = S3*x*z;
    o[1] = S3*x*y;
    o[2] = y*y - 0.5f*(x*x + z*z);
    o[3] = S3*y*z;
    o[4] = HS3*(z*z - x*x);
}

// ---------------- packed f32x2 primitives ----------------
__device__ __forceinline__ u64 fma2(u64 a, u64 b, u64 c) {
    u64 d;
    asm("fma.rn.f32x2 %0, %1, %2, %3;" : "=l"(d) : "l"(a), "l"(b), "l"(c));
    return d;
}
__device__ __forceinline__ u64 pk2(float x) {
    u64 d;
    asm("mov.b64 %0, {%1, %1};" : "=l"(d) : "r"(__float_as_uint(x)));
    return d;
}
__device__ __forceinline__ float2 up2(u64 v) {
    float2 f;
    asm("mov.b64 {%0, %1}, %2;" : "=f"(f.x), "=f"(f.y) : "l"(v));
    return f;
}

// ============ 64-row GEMM core (8 rows x 4 cols per thread, broadcast a) =====
// As: [64][132]. Ws: [128 k][132]. ty=tid>>5 (warp), r0=ty*8; tx=tid&31, c0=tx*4.
__device__ __forceinline__ void mm64(const float* __restrict__ As,
                                     const float* __restrict__ Ws,
                                     int r0, int c0, u64 acc[8][2]) {
    #pragma unroll
    for (int i = 0; i < 8; i++) { acc[i][0] = 0ull; acc[i][1] = 0ull; }
    const float* ap = As + r0*132;
    const float* wp = Ws + c0;
    #pragma unroll 4
    for (int k0 = 0; k0 < 128; k0 += 2) {
        float2 a2[8];
        #pragma unroll
        for (int i = 0; i < 8; i++)
            a2[i] = *(const float2*)(ap + i*132 + k0);
        ulonglong2 p0 = *(const ulonglong2*)(wp + k0*132);
        ulonglong2 q0 = *(const ulonglong2*)(wp + (k0+1)*132);
        #pragma unroll
        for (int i = 0; i < 8; i++) {
            u64 ax = pk2(a2[i].x);
            acc[i][0] = fma2(ax, p0.x, acc[i][0]);
            acc[i][1] = fma2(ax, p0.y, acc[i][1]);
        }
        #pragma unroll
        for (int i = 0; i < 8; i++) {
            u64 ay = pk2(a2[i].y);
            acc[i][0] = fma2(ay, q0.x, acc[i][0]);
            acc[i][1] = fma2(ay, q0.y, acc[i][1]);
        }
    }
}

// ============ 128-row node GEMM core (8x8, from round 3 — unchanged) =========
__device__ __forceinline__ void mm_cp(const float* __restrict__ As,
                                      const float* __restrict__ Ws,
                                      int r0, int c0, u64 acc[8][4]) {
    #pragma unroll
    for (int i = 0; i < 8; i++)
        #pragma unroll
        for (int j = 0; j < 4; j++) acc[i][j] = 0ull;
    const float* ap = As + r0*132;
    const float* wp = Ws + c0;
    #pragma unroll 2
    for (int k0 = 0; k0 < 128; k0 += 2) {
        float2 a2[8];
        #pragma unroll
        for (int i = 0; i < 8; i++)
            a2[i] = *(const float2*)(ap + i*132 + k0);
        const float* w0 = wp + k0*132;
        ulonglong2 p0 = *(const ulonglong2*)(w0);
        ulonglong2 p1 = *(const ulonglong2*)(w0 + 4);
        ulonglong2 q0 = *(const ulonglong2*)(w0 + 132);
        ulonglong2 q1 = *(const ulonglong2*)(w0 + 136);
        #pragma unroll
        for (int i = 0; i < 8; i++) {
            u64 ax = pk2(a2[i].x);
            acc[i][0] = fma2(ax, p0.x, acc[i][0]);
            acc[i][1] = fma2(ax, p0.y, acc[i][1]);
            acc[i][2] = fma2(ax, p1.x, acc[i][2]);
            acc[i][3] = fma2(ax, p1.y, acc[i][3]);
        }
        #pragma unroll
        for (int i = 0; i < 8; i++) {
            u64 ay = pk2(a2[i].y);
            acc[i][0] = fma2(ay, q0.x, acc[i][0]);
            acc[i][1] = fma2(ay, q0.y, acc[i][1]);
            acc[i][2] = fma2(ay, q1.x, acc[i][2]);
            acc[i][3] = fma2(ay, q1.y, acc[i][3]);
        }
    }
}

// ---------------- weight pad-copy ----------------
__global__ void pad_weights_kernel(const float* __restrict__ Wm1,
                                   const float* __restrict__ Wm2,
                                   const float* __restrict__ Wp1,
                                   const float* __restrict__ Ws1,
                                   const float* __restrict__ Wn1,
                                   const float* __restrict__ Wn2) {
    int bid = blockIdx.x;
    int l = bid >> 3, slot = bid & 7;
    const float* src;
    switch (slot) {
        case 0: src = Wm1 + (size_t)l*260*128;           break;
        case 1: src = Wm1 + ((size_t)l*260 + 128)*128;   break;
        case 2: src = Wm2 + (size_t)l*128*128;           break;
        case 3: src = Wp1 + (size_t)l*128*128;           break;
        case 4: src = Ws1 + (size_t)l*128*128;           break;
        case 5: src = Wn1 + (size_t)l*256*128;           break;
        case 6: src = Wn1 + ((size_t)l*256 + 128)*128;   break;
        default:src = Wn2 + (size_t)l*128*128;           break;
    }
    float* dst = g_Wt + (size_t)bid*128*132;
    for (int o = threadIdx.x; o < 128*132; o += 256) {
        int k = o / 132, c = o - k*132;
        dst[o] = (c < 128) ? src[k*128 + c] : 0.0f;
    }
}

// ---------------- generic node GEMM ----------------
#define GEMM2_SMEM (2*128*132*4)
__global__ void __launch_bounds__(256)
gemm2_kernel(const float* __restrict__ A, const float* __restrict__ Wk,
             const float* __restrict__ bias, const float* __restrict__ Cin,
             float* __restrict__ C, int M, int act) {
    extern __shared__ float sm[];
    float* As = sm;
    float* Ws = sm + 128*132;
    int tid = threadIdx.x;
    int row0 = blockIdx.x * 128;

    for (int idx = tid; idx < 128*32; idx += 256) {
        int r = idx >> 5, c4 = (idx & 31) * 4;
        float4 v = make_float4(0.f, 0.f, 0.f, 0.f);
        if (row0 + r < M) v = *(const float4*)(A + (size_t)(row0 + r)*128 + c4);
        *(float4*)(As + r*132 + c4) = v;
    }
    for (int idx = tid; idx < 128*33; idx += 256)
        *(float4*)(Ws + idx*4) = *(const float4*)(Wk + (size_t)idx*4);
    __syncthreads();

    int tx = tid & 15, ty = tid >> 4;
    int r0 = ty * 8, c0 = tx * 8;
    u64 acc[8][4];
    mm_cp(As, Ws, r0, c0, acc);

    #pragma unroll
    for (int i = 0; i < 8; i++) {
        int r = row0 + r0 + i;
        if (r >= M) continue;
        #pragma unroll
        for (int j = 0; j < 4; j++) {
            float2 f = up2(acc[i][j]);
            int c = c0 + 2*j;
            float v0 = f.x, v1 = f.y;
            if (Cin) {
                v0 += Cin[(size_t)r*128 + c];
                v1 += Cin[(size_t)r*128 + c + 1];
            }
            if (bias) { v0 += bias[c]; v1 += bias[c+1]; }
            if (act)  { v0 = silu_f(v0); v1 = silu_f(v1); }
            C[(size_t)r*128 + c]     = v0;
            C[(size_t)r*128 + c + 1] = v1;
        }
    }
}

// ---------------- init kernels ----------------
__global__ void node_init_kernel(const int* __restrict__ atoms, const float* __restrict__ emb) {
    int idx = blockIdx.x*256 + threadIdx.x;
    int i = idx >> 7, d = idx & 127;
    g_feat[idx] = emb[atoms[i]*128 + d];
}

__global__ void com_kernel(const int* __restrict__ batch) {
    int i = blockIdx.x*256 + threadIdx.x;
    if (i >= Nn) return;
    int b = batch[i];
    atomicAdd(&g_com[b*3+0], g_pos[i*3+0]);
    atomicAdd(&g_com[b*3+1], g_pos[i*3+1]);
    atomicAdd(&g_com[b*3+2], g_pos[i*3+2]);
    atomicAdd(&g_cnt[b], 1.0f);
}

__global__ void deg_kernel(const int* __restrict__ ei) {
    int e = blockIdx.x*256 + threadIdx.x;
    if (e >= Ee) return;
    atomicAdd(&g_deg[ei[e]], 1.0f);
}

__global__ void vocab_kernel(const float* __restrict__ emb, const float* __restrict__ Wsi1,
                             const float* __restrict__ WsiC1, const float* __restrict__ bsiC1,
                             const float* __restrict__ WsiC2, const float* __restrict__ bsiC2) {
    __shared__ float es[128];
    __shared__ float redv[128];
    int v = blockIdx.x, j = threadIdx.x;
    es[j] = emb[v*128 + j];
    __syncthreads();
    float p1 = 0.f, p2 = 0.f, hc = 0.f;
    for (int k = 0; k < 128; k++) {
        float e = es[k];
        p1 = fmaf(e, Wsi1[(1 + k)*128 + j], p1);
        p2 = fmaf(e, Wsi1[(129 + k)*128 + j], p2);
        hc = fmaf(e, WsiC1[k*128 + j], hc);
    }
    g_P1[v*128 + j] = p1;
    g_P2[v*128 + j] = p2;
    hc = silu_f(hc + bsiC1[j]);
    redv[j] = hc * WsiC2[j*3 + 2];
    __syncthreads();
    for (int s = 64; s > 0; s >>= 1) {
        if (j < s) redv[j] += redv[j + s];
        __syncthreads();
    }
    if (j == 0) g_cmsg[v] = redv[0] + bsiC2[2];
}

__global__ void edge_init_kernel(const int* __restrict__ ei, const int* __restrict__ atoms,
                                 const float* __restrict__ Wsi1, const float* __restrict__ bsi1,
                                 const float* __restrict__ Wsi2, const float* __restrict__ bsi2) {
    int e = blockIdx.x*8 + (threadIdx.x >> 5);
    int lane = threadIdx.x & 31;
    int r = ei[e], c = ei[Ee + e];
    float dp0 = g_pos[r*3+0] - g_pos[c*3+0];
    float dp1 = g_pos[r*3+1] - g_pos[c*3+1];
    float dp2 = g_pos[r*3+2] - g_pos[c*3+2];
    float dist = sqrtf(dp0*dp0 + dp1*dp1 + dp2*dp2);
    int ar = atoms[r], ac = atoms[c];
    float partial = 0.f;
    #pragma unroll
    for (int q = 0; q < 4; q++) {
        int d = lane + q*32;
        float h = silu_f(dist*Wsi1[d] + g_P1[ar*128 + d] + g_P2[ac*128 + d] + bsi1[d]);
        partial = fmaf(h, Wsi2[d*3 + 2], partial);
    }
    #pragma unroll
    for (int off = 16; off > 0; off >>= 1)
        partial += __shfl_xor_sync(0xffffffffu, partial, off);
    if (lane == 0) {
        float msg2 = partial + bsi2[2];
        float y2[5];
        sph2(dp0, dp1, dp2, y2);
        #pragma unroll
        for (int q = 0; q < 5; q++)
            atomicAdd(&g_ssum[r*9 + 4 + q], y2[q]*msg2);
    }
}

__global__ void sh_init_kernel(const int* __restrict__ atoms, const int* __restrict__ batch) {
    int i = blockIdx.x*256 + threadIdx.x;
    if (i >= Nn) return;
    float dg = fmaxf(g_deg[i], 1.0f);
    int b = batch[i];
    float cn = fmaxf(g_cnt[b], 1.0f);
    float vx = g_pos[i*3+0] - g_com[b*3+0]/cn;
    float vy = g_pos[i*3+1] - g_com[b*3+1]/cn;
    float vz = g_pos[i*3+2] - g_com[b*3+2]/cn;
    float y2[5];
    sph2(vx, vy, vz, y2);
    float cm = g_cmsg[atoms[i]];
    #pragma unroll
    for (int q = 0; q < 4; q++) g_sh[i*9 + q] = 0.0f;
    #pragma unroll
    for (int q = 0; q < 5; q++)
        g_sh[i*9 + 4 + q] = g_ssum[i*9 + 4 + q]/dg + cm*y2[q];
}

// ============ E1: persistent h-build + m-GEMM (weights resident) =============
// smem floats: Wt 16896 + h_s 8448 + bh 128 + wtl 640 + scal 256 = 26368 (+128 ints)
#define E1_SMEM (26368*4 + 128*4)
__global__ void __launch_bounds__(256)
edge_hm_kernel(const int* __restrict__ ei,
               const float* __restrict__ Wk_m2, const float* __restrict__ bm2l,
               const float* __restrict__ Wm1tail, const float* __restrict__ bm1l) {
    extern __shared__ float sm[];
    float* Wt   = sm;             // 16896
    float* h_s  = Wt + 16896;     // 8448
    float* bh   = h_s + 8448;     // 128
    float* wtl  = bh + 128;       // 640
    float* scal = wtl + 640;      // 256
    int*   ridx = (int*)(scal + 256);  // 64
    int*   cidx = ridx + 64;           // 64

    int tid = threadIdx.x;
    // one-time fills (visible after first loop-top sync)
    for (int idx = tid; idx < 128*33; idx += 256)
        *(float4*)(Wt + idx*4) = *(const float4*)(Wk_m2 + idx*4);
    if (tid < 128) bh[tid] = bm2l[tid];
    for (int idx = tid; idx < 640; idx += 256)
        wtl[idx] = (idx < 512) ? Wm1tail[idx] : bm1l[idx - 512];

    int ty = tid >> 5, tx = tid & 31;
    int r0 = ty*8, c0 = tx*4;

    for (int t = blockIdx.x; t < NTILES; t += gridDim.x) {
        int e0 = t*64;
        __syncthreads();   // protects h_s/scal/idx reuse + first-iter fills
        if (tid < 64) {
            int r = ei[e0 + tid], c = ei[Ee + e0 + tid];
            ridx[tid] = r; cidx[tid] = c;
            float dp0 = g_pos[r*3+0] - g_pos[c*3+0];
            float dp1 = g_pos[r*3+1] - g_pos[c*3+1];
            float dp2 = g_pos[r*3+2] - g_pos[c*3+2];
            float d2 = dp0*dp0 + dp1*dp1 + dp2*dp2;
            float ip0 = g_sh[r*9+0]*g_sh[c*9+0];
            float ip1 = g_sh[r*9+1]*g_sh[c*9+1] + g_sh[r*9+2]*g_sh[c*9+2] + g_sh[r*9+3]*g_sh[c*9+3];
            float ip2 = 0.f;
            #pragma unroll
            for (int q = 4; q < 9; q++) ip2 += g_sh[r*9+q]*g_sh[c*9+q];
            scal[tid*4+0] = d2; scal[tid*4+1] = ip0; scal[tid*4+2] = ip1; scal[tid*4+3] = ip2;
        }
        __syncthreads();
        // build h tile
        for (int idx = tid; idx < 64*32; idx += 256) {
            int e = idx >> 5, c4 = (idx & 31) * 4;
            int r = ridx[e], c = cidx[e];
            float4 fa = *(const float4*)(g_featA + (size_t)r*128 + c4);
            float4 fb = *(const float4*)(g_featB + (size_t)c*128 + c4);
            float d2 = scal[e*4+0], i0 = scal[e*4+1], i1 = scal[e*4+2], i2 = scal[e*4+3];
            float4 o;
            o.x = silu_f(fa.x + fb.x + d2*wtl[c4+0] + i0*wtl[128+c4+0] + i1*wtl[256+c4+0] + i2*wtl[384+c4+0] + wtl[512+c4+0]);
            o.y = silu_f(fa.y + fb.y + d2*wtl[c4+1] + i0*wtl[128+c4+1] + i1*wtl[256+c4+1] + i2*wtl[384+c4+1] + wtl[512+c4+1]);
            o.z = silu_f(fa.z + fb.z + d2*wtl[c4+2] + i0*wtl[128+c4+2] + i1*wtl[256+c4+2] + i2*wtl[384+c4+2] + wtl[512+c4+2]);
            o.w = silu_f(fa.w + fb.w + d2*wtl[c4+3] + i0*wtl[128+c4+3] + i1*wtl[256+c4+3] + i2*wtl[384+c4+3] + wtl[512+c4+3]);
            *(float4*)(h_s + e*132 + c4) = o;
        }
        __syncthreads();
        // m = silu(h @ Wm2 + bm2): write to gmem + reduce into msum, all from regs
        u64 acc[8][2];
        mm64(h_s, Wt, r0, c0, acc);
        #pragma unroll
        for (int i = 0; i < 8; i++) {
            int e = r0 + i;
            float2 f0 = up2(acc[i][0]);
            float2 f1 = up2(acc[i][1]);
            float4 mv;
            mv.x = silu_f(f0.x + bh[c0]);
            mv.y = silu_f(f0.y + bh[c0+1]);
            mv.z = silu_f(f1.x + bh[c0+2]);
            mv.w = silu_f(f1.y + bh[c0+3]);
            *(float4*)(g_m + (size_t)(e0 + e)*128 + c0) = mv;
            float* dst = g_msum + (size_t)ridx[e]*128 + c0;
            asm volatile("red.global.add.v4.f32 [%0], {%1, %2, %3, %4};"
                         :: "l"(dst), "f"(mv.x), "f"(mv.y), "f"(mv.z), "f"(mv.w)
                         : "memory");
        }
    }
}

// ============ E2: persistent p+s GEMMs, cp.async double-buffered m ===========
// smem floats: Wp 16896 + Ws 16896 + mbuf 2*8448 + 768 = 51456
#define E2_SMEM (51456*4)
__global__ void __launch_bounds__(256)
edge_ps_kernel(const int* __restrict__ ei,
               const float* __restrict__ Wk_p1, const float* __restrict__ bp1l,
               const float* __restrict__ Wp2l,  const float* __restrict__ bp2l,
               const float* __restrict__ Wk_s1, const float* __restrict__ bs1l,
               const float* __restrict__ Ws2l,  const float* __restrict__ bs2l) {
    extern __shared__ float sm[];
    float* Wp  = sm;              // 16896
    float* Ws  = Wp + 16896;      // 16896
    float* mb  = Ws + 16896;      // 2*8448
    float* bhp = mb + 16896;      // 128
    float* bhs = bhp + 128;       // 128
    float* w2p = bhs + 128;       // 128
    float* w2s = w2p + 128;       // 384

    int tid = threadIdx.x;
    for (int idx = tid; idx < 128*33; idx += 256) {
        *(float4*)(Wp + idx*4) = *(const float4*)(Wk_p1 + idx*4);
        *(float4*)(Ws + idx*4) = *(const float4*)(Wk_s1 + idx*4);
    }
    if (tid < 128) {
        bhp[tid] = bp1l[tid];
        bhs[tid] = bs1l[tid];
        w2p[tid] = Wp2l[tid];
        w2s[tid*3+0] = Ws2l[tid*3+0];
        w2s[tid*3+1] = Ws2l[tid*3+1];
        w2s[tid*3+2] = Ws2l[tid*3+2];
    }

    unsigned mb_u32 = (unsigned)__cvta_generic_to_shared(mb);
    int ty = tid >> 5, tx = tid & 31;
    int r0 = ty*8, c0 = tx*4;
    int stride = gridDim.x;
    int t0 = blockIdx.x;

    // prefetch first tile into buf 0
    if (t0 < NTILES) {
        int e0 = t0*64;
        #pragma unroll
        for (int q = 0; q < 8; q++) {
            int chunk = tid + q*256;
            int e = chunk >> 5, c16 = chunk & 31;
            const float* src = g_m + (size_t)(e0 + e)*128 + c16*4;
            unsigned dst = mb_u32 + (unsigned)(e*132 + c16*4)*4u;
            asm volatile("cp.async.cg.shared.global [%0], [%1], 16;" :: "r"(dst), "l"(src));
        }
        asm volatile("cp.async.commit_group;");
    }

    int it = 0;
    for (int t = t0; t < NTILES; t += stride, it++) {
        int buf = it & 1;
        bool pref = (t + stride < NTILES);
        if (pref) {
            int e0n = (t + stride)*64;
            unsigned base = mb_u32 + (unsigned)((buf ^ 1)*8448)*4u;
            #pragma unroll
            for (int q = 0; q < 8; q++) {
                int chunk = tid + q*256;
                int e = chunk >> 5, c16 = chunk & 31;
                const float* src = g_m + (size_t)(e0n + e)*128 + c16*4;
                unsigned dst = base + (unsigned)(e*132 + c16*4)*4u;
                asm volatile("cp.async.cg.shared.global [%0], [%1], 16;" :: "r"(dst), "l"(src));
            }
            asm volatile("cp.async.commit_group;");
            asm volatile("cp.async.wait_group 1;");
        } else {
            asm volatile("cp.async.wait_group 0;");
        }
        __syncthreads();   // current buf ready + weight fills (first iter)

        const float* ms = mb + buf*8448;
        int e0 = t*64;

        // GEMM p -> per-thread partial
        float pp[8];
        {
            u64 acc[8][2];
            mm64(ms, Wp, r0, c0, acc);
            #pragma unroll
            for (int i = 0; i < 8; i++) {
                float2 f0 = up2(acc[i][0]);
                float2 f1 = up2(acc[i][1]);
                pp[i] = silu_f(f0.x + bhp[c0])*w2p[c0]
                      + silu_f(f0.y + bhp[c0+1])*w2p[c0+1]
                      + silu_f(f1.x + bhp[c0+2])*w2p[c0+2]
                      + silu_f(f1.y + bhp[c0+3])*w2p[c0+3];
            }
        }
        // GEMM s -> 3-channel partials
        float ps[8][3];
        {
            u64 acc[8][2];
            mm64(ms, Ws, r0, c0, acc);
            #pragma unroll
            for (int i = 0; i < 8; i++) {
                float2 f0 = up2(acc[i][0]);
                float2 f1 = up2(acc[i][1]);
                float h0 = silu_f(f0.x + bhs[c0]);
                float h1 = silu_f(f0.y + bhs[c0+1]);
                float h2 = silu_f(f1.x + bhs[c0+2]);
                float h3 = silu_f(f1.y + bhs[c0+3]);
                #pragma unroll
                for (int ch = 0; ch < 3; ch++)
                    ps[i][ch] = h0*w2s[c0*3+ch] + h1*w2s[(c0+1)*3+ch]
                              + h2*w2s[(c0+2)*3+ch] + h3*w2s[(c0+3)*3+ch];
            }
        }
        // butterfly reduce over 32 lanes; lane i keeps row i's totals
        float my_p = 0.f, my_s0 = 0.f, my_s1 = 0.f, my_s2 = 0.f;
        #pragma unroll
        for (int i = 0; i < 8; i++) {
            float v0 = pp[i], v1 = ps[i][0], v2 = ps[i][1], v3 = ps[i][2];
            #pragma unroll
            for (int off = 16; off > 0; off >>= 1) {
                v0 += __shfl_xor_sync(0xffffffffu, v0, off);
                v1 += __shfl_xor_sync(0xffffffffu, v1, off);
                v2 += __shfl_xor_sync(0xffffffffu, v2, off);
                v3 += __shfl_xor_sync(0xffffffffu, v3, off);
            }
            if (tx == i) { my_p = v0; my_s0 = v1; my_s1 = v2; my_s2 = v3; }
        }
        // lanes 0..7 of each warp scatter for their edge
        if (tx < 8) {
            int e = e0 + r0 + tx;
            int r = ei[e], c = ei[Ee + e];
            float psc = my_p + bp2l[0];
            float s0 = my_s0 + bs2l[0];
            float s1 = my_s1 + bs2l[1];
            float s2 = my_s2 + bs2l[2];
            float dp0 = g_pos[r*3+0] - g_pos[c*3+0];
            float dp1 = g_pos[r*3+1] - g_pos[c*3+1];
            float dp2 = g_pos[r*3+2] - g_pos[c*3+2];
            atomicAdd(&g_psum[r*3+0], dp0*psc);
            atomicAdd(&g_psum[r*3+1], dp1*psc);
            atomicAdd(&g_psum[r*3+2], dp2*psc);
            #pragma unroll
            for (int q = 0; q < 9; q++) {
                float diff = g_sh[r*9 + q] - g_sh[c*9 + q];
                float w = (q == 0) ? s0 : (q < 4) ? s1 : s2;
                atomicAdd(&g_ssum[r*9 + q], diff*w);
            }
        }
        __syncthreads();   // all reads of buf done before it's prefetch-overwritten
    }
}

__global__ void divm_kernel() {
    int idx = blockIdx.x*256 + threadIdx.x;
    g_msum[idx] /= fmaxf(g_deg[idx >> 7], 1.0f);
}

__global__ void posh_kernel() {
    int i = blockIdx.x*256 + threadIdx.x;
    if (i >= Nn) return;
    float inv = 1.0f / fmaxf(g_deg[i], 1.0f);
    #pragma unroll
    for (int q = 0; q < 3; q++) g_pos[i*3 + q] += g_psum[i*3 + q]*inv;
    #pragma unroll
    for (int q = 0; q < 9; q++) g_sh[i*9 + q] += g_ssum[i*9 + q]*inv;
}

// ---------------- readout ----------------
__global__ void pool_kernel(const int* __restrict__ batch) {
    int idx = blockIdx.x*256 + threadIdx.x;
    if (idx >= Nn*140) return;
    int i = idx / 140, c = idx % 140;
    float v;
    if (c < 128)      v = g_feat[(size_t)i*128 + c];
    else if (c < 131) v = g_pos[i*3 + (c - 128)];
    else              v = g_sh[i*9 + (c - 131)];
    atomicAdd(&g_pool[batch[i]*140 + c], v);
}

__global__ void pred_kernel(const float* __restrict__ Wpred, const float* __restrict__ bpred,
                            float* __restrict__ out) {
    int g = blockIdx.x, lane = threadIdx.x;
    float s = 0.f;
    for (int c = lane; c < 140; c += 32)
        s = fmaf(g_pool[g*140 + c], Wpred[c], s);
    #pragma unroll
    for (int off = 16; off > 0; off >>= 1)
        s += __shfl_xor_sync(0xffffffffu, s, off);
    if (lane == 0) out[g] = s + bpred[0];
}

// ---------------- host ----------------
extern "C" void kernel_launch(void* const* d_in, const int* in_sizes, int n_in,
                              void* d_out, int out_size) {
    const int*   atoms = (const int*)d_in[0];
    const int*   ei    = (const int*)d_in[1];
    const int*   batch = (const int*)d_in[2];
    const float* pos   = (const float*)d_in[3];
    const float* emb   = (const float*)d_in[4];
    const float* Wsi1  = (const float*)d_in[5];  const float* bsi1  = (const float*)d_in[6];
    const float* Wsi2  = (const float*)d_in[7];  const float* bsi2  = (const float*)d_in[8];
    const float* WsiC1 = (const float*)d_in[9];  const float* bsiC1 = (const float*)d_in[10];
    const float* WsiC2 = (const float*)d_in[11]; const float* bsiC2 = (const float*)d_in[12];
    const float* Wm1   = (const float*)d_in[13]; const float* bm1   = (const float*)d_in[14];
    const float* Wm2   = (const float*)d_in[15]; const float* bm2   = (const float*)d_in[16];
    const float* Wp1   = (const float*)d_in[17]; const float* bp1   = (const float*)d_in[18];
    const float* Wp2   = (const float*)d_in[19]; const float* bp2   = (const float*)d_in[20];
    const float* Wn1   = (const float*)d_in[21]; const float* bn1   = (const float*)d_in[22];
    const float* Wn2   = (const float*)d_in[23]; const float* bn2   = (const float*)d_in[24];
    const float* Ws1   = (const float*)d_in[25]; const float* bs1   = (const float*)d_in[26];
    const float* Ws2   = (const float*)d_in[27]; const float* bs2   = (const float*)d_in[28];
    const float* Wpred = (const float*)d_in[29]; const float* bpred = (const float*)d_in[30];
    float* out = (float*)d_out;

    cudaFuncSetAttribute(gemm2_kernel, cudaFuncAttributeMaxDynamicSharedMemorySize, GEMM2_SMEM);
    cudaFuncSetAttribute(edge_hm_kernel, cudaFuncAttributeMaxDynamicSharedMemorySize, E1_SMEM);
    cudaFuncSetAttribute(edge_ps_kernel, cudaFuncAttributeMaxDynamicSharedMemorySize, E2_SMEM);

    void *p_msum, *p_psum, *p_ssum, *p_deg, *p_com, *p_cnt, *p_pool, *p_pos;
    void *p_feat, *p_featA, *p_featB, *p_tmp, *p_Wt;
    cudaGetSymbolAddress(&p_msum, g_msum);
    cudaGetSymbolAddress(&p_psum, g_psum);
    cudaGetSymbolAddress(&p_ssum, g_ssum);
    cudaGetSymbolAddress(&p_deg,  g_deg);
    cudaGetSymbolAddress(&p_com,  g_com);
    cudaGetSymbolAddress(&p_cnt,  g_cnt);
    cudaGetSymbolAddress(&p_pool, g_pool);
    cudaGetSymbolAddress(&p_pos,  g_pos);
    cudaGetSymbolAddress(&p_feat,  g_feat);
    cudaGetSymbolAddress(&p_featA, g_featA);
    cudaGetSymbolAddress(&p_featB, g_featB);
    cudaGetSymbolAddress(&p_tmp,   g_tmp);
    cudaGetSymbolAddress(&p_Wt,    g_Wt);
    const float* Wtb = (const float*)p_Wt;

    cudaMemsetAsync(p_deg,  0, Nn*4, 0);
    cudaMemsetAsync(p_com,  0, Gg*3*4, 0);
    cudaMemsetAsync(p_cnt,  0, Gg*4, 0);
    cudaMemsetAsync(p_ssum, 0, Nn*9*4, 0);
    cudaMemsetAsync(p_pool, 0, Gg*140*4, 0);
    cudaMemcpyAsync(p_pos, pos, Nn*3*4, cudaMemcpyDeviceToDevice, 0);

    pad_weights_kernel<<<Ll*8, 256>>>(Wm1, Wm2, Wp1, Ws1, Wn1, Wn2);
    node_init_kernel<<<(Nn*128)/256, 256>>>(atoms, emb);
    com_kernel<<<(Nn + 255)/256, 256>>>(batch);
    deg_kernel<<<(Ee + 255)/256, 256>>>(ei);
    vocab_kernel<<<10, 128>>>(emb, Wsi1, WsiC1, bsiC1, WsiC2, bsiC2);
    edge_init_kernel<<<Ee/8, 256>>>(ei, atoms, Wsi1, bsi1, Wsi2, bsi2);
    sh_init_kernel<<<(Nn + 255)/256, 256>>>(atoms, batch);

    int gridN = (Nn + 127)/128;  // 79
    const size_t SLOT = 128*132;

    for (int l = 0; l < Ll; l++) {
        cudaMemsetAsync(p_msum, 0, (size_t)Nn*128*4, 0);
        cudaMemsetAsync(p_psum, 0, Nn*3*4, 0);
        cudaMemsetAsync(p_ssum, 0, Nn*9*4, 0);

        const float* Wl = Wtb + (size_t)l*8*SLOT;

        gemm2_kernel<<<gridN, 256, GEMM2_SMEM>>>(
            (const float*)p_feat, Wl + 0*SLOT, nullptr, nullptr, (float*)p_featA, Nn, 0);
        gemm2_kernel<<<gridN, 256, GEMM2_SMEM>>>(
            (const float*)p_feat, Wl + 1*SLOT, nullptr, nullptr, (float*)p_featB, Nn, 0);

        edge_hm_kernel<<<296, 256, E1_SMEM>>>(
            ei, Wl + 2*SLOT, bm2 + l*128,
            Wm1 + ((size_t)l*260 + 256)*128, bm1 + l*128);

        edge_ps_kernel<<<148, 256, E2_SMEM>>>(
            ei,
            Wl + 3*SLOT, bp1 + l*128, Wp2 + l*128, bp2 + l,
            Wl + 4*SLOT, bs1 + l*128, Ws2 + l*384, bs2 + l*3);

        divm_kernel<<<(Nn*128)/256, 256>>>();
        posh_kernel<<<(Nn + 255)/256, 256>>>();

        gemm2_kernel<<<gridN, 256, GEMM2_SMEM>>>(
            (const float*)p_feat, Wl + 5*SLOT, nullptr, nullptr, (float*)p_tmp, Nn, 0);
        gemm2_kernel<<<gridN, 256, GEMM2_SMEM>>>(
            (const float*)p_msum, Wl + 6*SLOT, bn1 + l*128,
            (const float*)p_tmp, (float*)p_tmp, Nn, 1);
        gemm2_kernel<<<gridN, 256, GEMM2_SMEM>>>(
            (const float*)p_tmp, Wl + 7*SLOT, bn2 + l*128, nullptr, (float*)p_feat, Nn, 0);
    }

    pool_kernel<<<(Nn*140 + 255)/256, 256>>>(batch);
    pred_kernel<<<Gg, 32>>>(Wpred, bpred, out);
}

// round 5
// speedup vs baseline: 1.7476x; 1.0652x over previous
#include <cuda_runtime.h>
#include <math.h>

#define Nn 10000
#define Ee 160000
#define Gg 100
#define Ll 5
#define NTILES 2500

typedef unsigned long long u64;

// ---------------- scratch (device globals) ----------------
__device__ float g_feat [Nn*128];
__device__ float g_featA[Nn*128];
__device__ float g_featB[Nn*128];
__device__ float g_sh   [Nn*9];
__device__ float g_pos  [Nn*3];
__device__ float g_msum [Nn*128];
__device__ float g_psum [Nn*3];
__device__ float g_ssum [Nn*9];
__device__ float g_deg  [Nn];
__device__ float g_com  [Gg*3];
__device__ float g_cnt  [Gg];
__device__ float g_P1   [10*128];
__device__ float g_P2   [10*128];
__device__ float g_cmsg [10];
__device__ float g_pool [Gg*140];
__device__ float g_m    [(size_t)Ee*128];
__device__ int   g_off  [Nn];
__device__ int   g_cursor[Nn];
__device__ int   g_er   [Ee];
__device__ int   g_ec   [Ee];

__device__ __forceinline__ float silu_f(float x) { return x / (1.0f + __expf(-x)); }

__device__ __forceinline__ void sph2(float vx, float vy, float vz, float* o) {
    const float S3  = 1.7320508075688772f;
    const float HS3 = 0.8660254037844386f;
    float r = sqrtf(vx*vx + vy*vy + vz*vz);
    float inv = 1.0f / fmaxf(r, 1e-12f);
    float x = vx*inv, y = vy*inv, z = vz*inv;
    o[0] = S3*x*z;
    o[1] = S3*x*y;
    o[2] = y*y - 0.5f*(x*x + z*z);
    o[3] = S3*y*z;
    o[4] = HS3*(z*z - x*x);
}

// ---------------- packed f32x2 primitives ----------------
__device__ __forceinline__ u64 fma2(u64 a, u64 b, u64 c) {
    u64 d;
    asm("fma.rn.f32x2 %0, %1, %2, %3;" : "=l"(d) : "l"(a), "l"(b), "l"(c));
    return d;
}
__device__ __forceinline__ u64 pk2(float x) {
    u64 d;
    asm("mov.b64 %0, {%1, %1};" : "=l"(d) : "r"(__float_as_uint(x)));
    return d;
}
__device__ __forceinline__ float2 up2(u64 v) {
    float2 f;
    asm("mov.b64 {%0, %1}, %2;" : "=f"(f.x), "=f"(f.y) : "l"(v));
    return f;
}

// ---- GEMM core: RPW rows (broadcast a), 4 cols/thread, stride 128, no-zero acc ----
template<int RPW>
__device__ __forceinline__ void mmk(const float* __restrict__ As,
                                    const float* __restrict__ Ws,
                                    int r0, int c0, u64 acc[RPW][2]) {
    const float* ap = As + r0*128;
    const float* wp = Ws + c0;
    #pragma unroll 4
    for (int k0 = 0; k0 < 128; k0 += 2) {
        float2 a2[RPW];
        #pragma unroll
        for (int i = 0; i < RPW; i++)
            a2[i] = *(const float2*)(ap + i*128 + k0);
        ulonglong2 p0 = *(const ulonglong2*)(wp + k0*128);
        ulonglong2 q0 = *(const ulonglong2*)(wp + (k0+1)*128);
        #pragma unroll
        for (int i = 0; i < RPW; i++) {
            u64 ax = pk2(a2[i].x);
            acc[i][0] = fma2(ax, p0.x, acc[i][0]);
            acc[i][1] = fma2(ax, p0.y, acc[i][1]);
        }
        #pragma unroll
        for (int i = 0; i < RPW; i++) {
            u64 ay = pk2(a2[i].y);
            acc[i][0] = fma2(ay, q0.x, acc[i][0]);
            acc[i][1] = fma2(ay, q0.y, acc[i][1]);
        }
    }
}

// ---------------- init kernels ----------------
__global__ void node_init_kernel(const int* __restrict__ atoms, const float* __restrict__ emb) {
    int idx = blockIdx.x*256 + threadIdx.x;
    int i = idx >> 7, d = idx & 127;
    g_feat[idx] = emb[atoms[i]*128 + d];
}

__global__ void com_kernel(const int* __restrict__ batch) {
    int i = blockIdx.x*256 + threadIdx.x;
    if (i >= Nn) return;
    int b = batch[i];
    atomicAdd(&g_com[b*3+0], g_pos[i*3+0]);
    atomicAdd(&g_com[b*3+1], g_pos[i*3+1]);
    atomicAdd(&g_com[b*3+2], g_pos[i*3+2]);
    atomicAdd(&g_cnt[b], 1.0f);
}

__global__ void deg_kernel(const int* __restrict__ ei) {
    int e = blockIdx.x*256 + threadIdx.x;
    if (e >= Ee) return;
    atomicAdd(&g_deg[ei[e]], 1.0f);
}

// exclusive prefix scan of deg -> g_off (single block)
__global__ void scan_kernel() {
    __shared__ int part[256];
    int tid = threadIdx.x;
    int lo = tid*40, hi = (lo + 40 < Nn) ? lo + 40 : Nn;
    int s = 0;
    for (int i = lo; i < hi; i++) s += (int)g_deg[i];
    part[tid] = s;
    __syncthreads();
    for (int off = 1; off < 256; off <<= 1) {
        int v = part[tid] + ((tid >= off) ? part[tid - off] : 0);
        __syncthreads();
        part[tid] = v;
        __syncthreads();
    }
    int base = (tid > 0) ? part[tid - 1] : 0;
    for (int i = lo; i < hi; i++) {
        g_off[i] = base;
        base += (int)g_deg[i];
    }
}

__global__ void sortscatter_kernel(const int* __restrict__ ei) {
    int e = blockIdx.x*256 + threadIdx.x;
    if (e >= Ee) return;
    int r = ei[e], c = ei[Ee + e];
    int p = g_off[r] + atomicAdd(&g_cursor[r], 1);
    g_er[p] = r;
    g_ec[p] = c;
}

__global__ void vocab_kernel(const float* __restrict__ emb, const float* __restrict__ Wsi1,
                             const float* __restrict__ WsiC1, const float* __restrict__ bsiC1,
                             const float* __restrict__ WsiC2, const float* __restrict__ bsiC2) {
    __shared__ float es[128];
    __shared__ float redv[128];
    int v = blockIdx.x, j = threadIdx.x;
    es[j] = emb[v*128 + j];
    __syncthreads();
    float p1 = 0.f, p2 = 0.f, hc = 0.f;
    for (int k = 0; k < 128; k++) {
        float e = es[k];
        p1 = fmaf(e, Wsi1[(1 + k)*128 + j], p1);
        p2 = fmaf(e, Wsi1[(129 + k)*128 + j], p2);
        hc = fmaf(e, WsiC1[k*128 + j], hc);
    }
    g_P1[v*128 + j] = p1;
    g_P2[v*128 + j] = p2;
    hc = silu_f(hc + bsiC1[j]);
    redv[j] = hc * WsiC2[j*3 + 2];
    __syncthreads();
    for (int s = 64; s > 0; s >>= 1) {
        if (j < s) redv[j] += redv[j + s];
        __syncthreads();
    }
    if (j == 0) g_cmsg[v] = redv[0] + bsiC2[2];
}

__global__ void edge_init_kernel(const int* __restrict__ atoms,
                                 const float* __restrict__ Wsi1, const float* __restrict__ bsi1,
                                 const float* __restrict__ Wsi2, const float* __restrict__ bsi2) {
    int e = blockIdx.x*8 + (threadIdx.x >> 5);
    int lane = threadIdx.x & 31;
    int r = g_er[e], c = g_ec[e];
    float dp0 = g_pos[r*3+0] - g_pos[c*3+0];
    float dp1 = g_pos[r*3+1] - g_pos[c*3+1];
    float dp2 = g_pos[r*3+2] - g_pos[c*3+2];
    float dist = sqrtf(dp0*dp0 + dp1*dp1 + dp2*dp2);
    int ar = atoms[r], ac = atoms[c];
    float partial = 0.f;
    #pragma unroll
    for (int q = 0; q < 4; q++) {
        int d = lane + q*32;
        float h = silu_f(dist*Wsi1[d] + g_P1[ar*128 + d] + g_P2[ac*128 + d] + bsi1[d]);
        partial = fmaf(h, Wsi2[d*3 + 2], partial);
    }
    #pragma unroll
    for (int off = 16; off > 0; off >>= 1)
        partial += __shfl_xor_sync(0xffffffffu, partial, off);
    if (lane == 0) {
        float msg2 = partial + bsi2[2];
        float y2[5];
        sph2(dp0, dp1, dp2, y2);
        #pragma unroll
        for (int q = 0; q < 5; q++)
            atomicAdd(&g_ssum[r*9 + 4 + q], y2[q]*msg2);
    }
}

__global__ void sh_init_kernel(const int* __restrict__ atoms, const int* __restrict__ batch) {
    int i = blockIdx.x*256 + threadIdx.x;
    if (i >= Nn) return;
    float dg = fmaxf(g_deg[i], 1.0f);
    int b = batch[i];
    float cn = fmaxf(g_cnt[b], 1.0f);
    float vx = g_pos[i*3+0] - g_com[b*3+0]/cn;
    float vy = g_pos[i*3+1] - g_com[b*3+1]/cn;
    float vz = g_pos[i*3+2] - g_com[b*3+2]/cn;
    float y2[5];
    sph2(vx, vy, vz, y2);
    float cm = g_cmsg[atoms[i]];
    #pragma unroll
    for (int q = 0; q < 4; q++) g_sh[i*9 + q] = 0.0f;
    #pragma unroll
    for (int q = 0; q < 5; q++)
        g_sh[i*9 + 4 + q] = g_ssum[i*9 + 4 + q]/dg + cm*y2[q];
}

// ============ featAB: featA = feat@Wa, featB = feat@Wb (shared A tile) =======
// smem: As 64*128 + Wa 128*128 + Wb 128*128 = 40960 floats = 160KB
#define FAB_SMEM ((64*128 + 2*128*128)*4)
__global__ void __launch_bounds__(256)
featab_kernel(const float* __restrict__ Wa, const float* __restrict__ Wb) {
    extern __shared__ float sm[];
    float* As  = sm;
    float* Was = As + 64*128;
    float* Wbs = Was + 128*128;
    int tid = threadIdx.x;
    int row0 = blockIdx.x * 64;

    for (int idx = tid; idx < 64*32; idx += 256) {
        int r = idx >> 5, c4 = (idx & 31) * 4;
        float4 v = make_float4(0.f, 0.f, 0.f, 0.f);
        if (row0 + r < Nn) v = *(const float4*)(g_feat + (size_t)(row0 + r)*128 + c4);
        *(float4*)(As + r*128 + c4) = v;
    }
    for (int idx = tid; idx < 128*32; idx += 256) {
        *(float4*)(Was + idx*4) = *(const float4*)(Wa + (size_t)idx*4);
        *(float4*)(Wbs + idx*4) = *(const float4*)(Wb + (size_t)idx*4);
    }
    __syncthreads();

    int ty = tid >> 5, tx = tid & 31;
    int r0 = ty*8, c0 = tx*4;
    u64 acc[8][2];
    #pragma unroll
    for (int i = 0; i < 8; i++) { acc[i][0] = 0ull; acc[i][1] = 0ull; }
    mmk<8>(As, Was, r0, c0, acc);
    #pragma unroll
    for (int i = 0; i < 8; i++) {
        int r = row0 + r0 + i;
        if (r >= Nn) continue;
        float2 f0 = up2(acc[i][0]), f1 = up2(acc[i][1]);
        *(float4*)(g_featA + (size_t)r*128 + c0) = make_float4(f0.x, f0.y, f1.x, f1.y);
    }
    #pragma unroll
    for (int i = 0; i < 8; i++) { acc[i][0] = 0ull; acc[i][1] = 0ull; }
    mmk<8>(As, Wbs, r0, c0, acc);
    #pragma unroll
    for (int i = 0; i < 8; i++) {
        int r = row0 + r0 + i;
        if (r >= Nn) continue;
        float2 f0 = up2(acc[i][0]), f1 = up2(acc[i][1]);
        *(float4*)(g_featB + (size_t)r*128 + c0) = make_float4(f0.x, f0.y, f1.x, f1.y);
    }
}

// ============ node update: feat = silu(feat@W5 + (msum/deg)@W6 + b1)@W7 + b2 =
// smem: A1 32K + A2 32K + Wx 64K + Wy 64K + biases = 192K+
#define NU_SMEM ((2*64*128 + 2*128*128 + 256)*4)
__global__ void __launch_bounds__(256)
nodeup_kernel(const float* __restrict__ W5, const float* __restrict__ W6,
              const float* __restrict__ W7,
              const float* __restrict__ b1, const float* __restrict__ b2) {
    extern __shared__ float sm[];
    float* A1  = sm;                 // 64*128 (feat, later H)
    float* A2  = A1 + 64*128;        // 64*128 (msum/deg)
    float* Wx  = A2 + 64*128;        // 128*128 (W5, later W7)
    float* Wy  = Wx + 128*128;       // 128*128 (W6)
    float* bb  = Wy + 128*128;       // 256
    int tid = threadIdx.x;
    int row0 = blockIdx.x * 64;

    for (int idx = tid; idx < 64*32; idx += 256) {
        int r = idx >> 5, c4 = (idx & 31) * 4;
        float4 v1 = make_float4(0.f,0.f,0.f,0.f), v2 = v1;
        if (row0 + r < Nn) {
            v1 = *(const float4*)(g_feat + (size_t)(row0 + r)*128 + c4);
            v2 = *(const float4*)(g_msum + (size_t)(row0 + r)*128 + c4);
            float inv = 1.0f / fmaxf(g_deg[row0 + r], 1.0f);
            v2.x *= inv; v2.y *= inv; v2.z *= inv; v2.w *= inv;
        }
        *(float4*)(A1 + r*128 + c4) = v1;
        *(float4*)(A2 + r*128 + c4) = v2;
    }
    for (int idx = tid; idx < 128*32; idx += 256) {
        *(float4*)(Wx + idx*4) = *(const float4*)(W5 + (size_t)idx*4);
        *(float4*)(Wy + idx*4) = *(const float4*)(W6 + (size_t)idx*4);
    }
    if (tid < 128) { bb[tid] = b1[tid]; bb[128 + tid] = b2[tid]; }
    __syncthreads();

    int ty = tid >> 5, tx = tid & 31;
    int r0 = ty*8, c0 = tx*4;
    u64 acc[8][2];
    #pragma unroll
    for (int i = 0; i < 8; i++) { acc[i][0] = 0ull; acc[i][1] = 0ull; }
    mmk<8>(A1, Wx, r0, c0, acc);
    mmk<8>(A2, Wy, r0, c0, acc);
    __syncthreads();   // done reading A1
    #pragma unroll
    for (int i = 0; i < 8; i++) {
        float2 f0 = up2(acc[i][0]), f1 = up2(acc[i][1]);
        A1[(r0 + i)*128 + c0 + 0] = silu_f(f0.x + bb[c0]);
        A1[(r0 + i)*128 + c0 + 1] = silu_f(f0.y + bb[c0+1]);
        A1[(r0 + i)*128 + c0 + 2] = silu_f(f1.x + bb[c0+2]);
        A1[(r0 + i)*128 + c0 + 3] = silu_f(f1.y + bb[c0+3]);
    }
    for (int idx = tid; idx < 128*32; idx += 256)
        *(float4*)(Wx + idx*4) = *(const float4*)(W7 + (size_t)idx*4);
    __syncthreads();

    #pragma unroll
    for (int i = 0; i < 8; i++) { acc[i][0] = 0ull; acc[i][1] = 0ull; }
    mmk<8>(A1, Wx, r0, c0, acc);
    #pragma unroll
    for (int i = 0; i < 8; i++) {
        int r = row0 + r0 + i;
        if (r >= Nn) continue;
        float2 f0 = up2(acc[i][0]), f1 = up2(acc[i][1]);
        *(float4*)(g_feat + (size_t)r*128 + c0) =
            make_float4(f0.x + bb[128+c0], f0.y + bb[128+c0+1],
                        f1.x + bb[128+c0+2], f1.y + bb[128+c0+3]);
    }
}

// ============ E1: persistent h-build + m-GEMM (sorted edges) =================
// smem: Wm2 64K + h 32K + wtl 2.5K + scal 1K + bh 0.5K + idx 0.5K ≈ 100.7K → 2 blocks/SM
#define E1_SMEM ((128*128 + 64*128 + 640 + 256 + 128)*4 + 128*4)
__global__ void __launch_bounds__(256)
edge_hm_kernel(const float* __restrict__ Wm2, const float* __restrict__ bm2l,
               const float* __restrict__ Wm1tail, const float* __restrict__ bm1l) {
    extern __shared__ float sm[];
    float* Wt   = sm;                 // 128*128
    float* h_s  = Wt + 128*128;       // 64*128
    float* wtl  = h_s + 64*128;       // 640
    float* scal = wtl + 640;          // 256
    float* bh   = scal + 256;         // 128
    int*   ridx = (int*)(bh + 128);   // 64
    int*   cidx = ridx + 64;          // 64

    int tid = threadIdx.x;
    for (int idx = tid; idx < 128*32; idx += 256)
        *(float4*)(Wt + idx*4) = *(const float4*)(Wm2 + (size_t)idx*4);
    if (tid < 128) bh[tid] = bm2l[tid];
    for (int idx = tid; idx < 640; idx += 256)
        wtl[idx] = (idx < 512) ? Wm1tail[idx] : bm1l[idx - 512];

    int ty = tid >> 5, tx = tid & 31;
    int r0 = ty*8, c0 = tx*4;

    for (int t = blockIdx.x; t < NTILES; t += gridDim.x) {
        int e0 = t*64;
        __syncthreads();
        if (tid < 64) {
            int r = g_er[e0 + tid], c = g_ec[e0 + tid];
            ridx[tid] = r; cidx[tid] = c;
            float dp0 = g_pos[r*3+0] - g_pos[c*3+0];
            float dp1 = g_pos[r*3+1] - g_pos[c*3+1];
            float dp2 = g_pos[r*3+2] - g_pos[c*3+2];
            float d2 = dp0*dp0 + dp1*dp1 + dp2*dp2;
            float ip0 = g_sh[r*9+0]*g_sh[c*9+0];
            float ip1 = g_sh[r*9+1]*g_sh[c*9+1] + g_sh[r*9+2]*g_sh[c*9+2] + g_sh[r*9+3]*g_sh[c*9+3];
            float ip2 = 0.f;
            #pragma unroll
            for (int q = 4; q < 9; q++) ip2 += g_sh[r*9+q]*g_sh[c*9+q];
            scal[tid*4+0] = d2; scal[tid*4+1] = ip0; scal[tid*4+2] = ip1; scal[tid*4+3] = ip2;
        }
        __syncthreads();
        // h-build: batch loads first (MLP), then compute
        {
            float4 fa[8], fb[8];
            #pragma unroll
            for (int q = 0; q < 8; q++) {
                int idx = tid + q*256;
                int e = idx >> 5, c4 = (idx & 31) * 4;
                fa[q] = *(const float4*)(g_featA + (size_t)ridx[e]*128 + c4);
                fb[q] = *(const float4*)(g_featB + (size_t)cidx[e]*128 + c4);
            }
            #pragma unroll
            for (int q = 0; q < 8; q++) {
                int idx = tid + q*256;
                int e = idx >> 5, c4 = (idx & 31) * 4;
                float d2 = scal[e*4+0], i0 = scal[e*4+1], i1 = scal[e*4+2], i2 = scal[e*4+3];
                float4 o;
                o.x = silu_f(fa[q].x + fb[q].x + d2*wtl[c4+0] + i0*wtl[128+c4+0] + i1*wtl[256+c4+0] + i2*wtl[384+c4+0] + wtl[512+c4+0]);
                o.y = silu_f(fa[q].y + fb[q].y + d2*wtl[c4+1] + i0*wtl[128+c4+1] + i1*wtl[256+c4+1] + i2*wtl[384+c4+1] + wtl[512+c4+1]);
                o.z = silu_f(fa[q].z + fb[q].z + d2*wtl[c4+2] + i0*wtl[128+c4+2] + i1*wtl[256+c4+2] + i2*wtl[384+c4+2] + wtl[512+c4+2]);
                o.w = silu_f(fa[q].w + fb[q].w + d2*wtl[c4+3] + i0*wtl[128+c4+3] + i1*wtl[256+c4+3] + i2*wtl[384+c4+3] + wtl[512+c4+3]);
                *(float4*)(h_s + e*128 + c4) = o;
            }
        }
        __syncthreads();
        u64 acc[8][2];
        #pragma unroll
        for (int i = 0; i < 8; i++) { acc[i][0] = 0ull; acc[i][1] = 0ull; }
        mmk<8>(h_s, Wt, r0, c0, acc);
        // store m + segmented RED into msum (sorted rows)
        float4 aggv = make_float4(0.f, 0.f, 0.f, 0.f);
        int agg_r = ridx[r0];
        #pragma unroll
        for (int i = 0; i < 8; i++) {
            int e = r0 + i;
            float2 f0 = up2(acc[i][0]);
            float2 f1 = up2(acc[i][1]);
            float4 mv;
            mv.x = silu_f(f0.x + bh[c0]);
            mv.y = silu_f(f0.y + bh[c0+1]);
            mv.z = silu_f(f1.x + bh[c0+2]);
            mv.w = silu_f(f1.y + bh[c0+3]);
            *(float4*)(g_m + (size_t)(e0 + e)*128 + c0) = mv;
            int r = ridx[e];
            if (r != agg_r) {
                float* dst = g_msum + (size_t)agg_r*128 + c0;
                asm volatile("red.global.add.v4.f32 [%0], {%1, %2, %3, %4};"
                             :: "l"(dst), "f"(aggv.x), "f"(aggv.y), "f"(aggv.z), "f"(aggv.w)
                             : "memory");
                aggv = mv; agg_r = r;
            } else {
                aggv.x += mv.x; aggv.y += mv.y; aggv.z += mv.z; aggv.w += mv.w;
            }
        }
        {
            float* dst = g_msum + (size_t)agg_r*128 + c0;
            asm volatile("red.global.add.v4.f32 [%0], {%1, %2, %3, %4};"
                         :: "l"(dst), "f"(aggv.x), "f"(aggv.y), "f"(aggv.z), "f"(aggv.w)
                         : "memory");
        }
    }
}

// ============ E2: persistent p+s GEMMs (512 threads, double-buffered m) ======
// smem: Wp 64K + Ws 64K + mb 2*32K + misc ≈ 195K → 1 block/SM
#define E2_SMEM ((2*128*128 + 2*64*128 + 768)*4)
__global__ void __launch_bounds__(512)
edge_ps_kernel(const float* __restrict__ Wk_p1, const float* __restrict__ bp1l,
               const float* __restrict__ Wp2l,  const float* __restrict__ bp2l,
               const float* __restrict__ Wk_s1, const float* __restrict__ bs1l,
               const float* __restrict__ Ws2l,  const float* __restrict__ bs2l) {
    extern __shared__ float sm[];
    float* Wp  = sm;                 // 128*128
    float* Ws  = Wp + 128*128;       // 128*128
    float* mb  = Ws + 128*128;       // 2*64*128
    float* bhp = mb + 2*64*128;      // 128
    float* bhs = bhp + 128;          // 128
    float* w2p = bhs + 128;          // 128
    float* w2s = w2p + 128;          // 384

    int tid = threadIdx.x;
    for (int idx = tid; idx < 128*32; idx += 512) {
        *(float4*)(Wp + idx*4) = *(const float4*)(Wk_p1 + (size_t)idx*4);
        *(float4*)(Ws + idx*4) = *(const float4*)(Wk_s1 + (size_t)idx*4);
    }
    if (tid < 128) {
        bhp[tid] = bp1l[tid];
        bhs[tid] = bs1l[tid];
        w2p[tid] = Wp2l[tid];
        w2s[tid*3+0] = Ws2l[tid*3+0];
        w2s[tid*3+1] = Ws2l[tid*3+1];
        w2s[tid*3+2] = Ws2l[tid*3+2];
    }

    unsigned mb_u32 = (unsigned)__cvta_generic_to_shared(mb);
    int w = tid >> 5, tx = tid & 31;
    int r0 = w*4, c0 = tx*4;
    int stride = gridDim.x;
    int t0 = blockIdx.x;

    if (t0 < NTILES) {
        int e0 = t0*64;
        #pragma unroll
        for (int q = 0; q < 4; q++) {
            int chunk = tid + q*512;
            const float* src = g_m + (size_t)e0*128 + chunk*4;
            unsigned dst = mb_u32 + (unsigned)chunk*16u;
            asm volatile("cp.async.cg.shared.global [%0], [%1], 16;" :: "r"(dst), "l"(src));
        }
        asm volatile("cp.async.commit_group;");
    }

    int it = 0;
    for (int t = t0; t < NTILES; t += stride, it++) {
        int buf = it & 1;
        bool pref = (t + stride < NTILES);
        if (pref) {
            int e0n = (t + stride)*64;
            unsigned base = mb_u32 + (unsigned)((buf ^ 1)*64*128)*4u;
            #pragma unroll
            for (int q = 0; q < 4; q++) {
                int chunk = tid + q*512;
                const float* src = g_m + (size_t)e0n*128 + chunk*4;
                unsigned dst = base + (unsigned)chunk*16u;
                asm volatile("cp.async.cg.shared.global [%0], [%1], 16;" :: "r"(dst), "l"(src));
            }
            asm volatile("cp.async.commit_group;");
            asm volatile("cp.async.wait_group 1;");
        } else {
            asm volatile("cp.async.wait_group 0;");
        }
        __syncthreads();

        const float* ms = mb + buf*64*128;
        int e0 = t*64;

        float pp[4];
        {
            u64 acc[4][2];
            #pragma unroll
            for (int i = 0; i < 4; i++) { acc[i][0] = 0ull; acc[i][1] = 0ull; }
            mmk<4>(ms, Wp, r0, c0, acc);
            #pragma unroll
            for (int i = 0; i < 4; i++) {
                float2 f0 = up2(acc[i][0]);
                float2 f1 = up2(acc[i][1]);
                pp[i] = silu_f(f0.x + bhp[c0])*w2p[c0]
                      + silu_f(f0.y + bhp[c0+1])*w2p[c0+1]
                      + silu_f(f1.x + bhp[c0+2])*w2p[c0+2]
                      + silu_f(f1.y + bhp[c0+3])*w2p[c0+3];
            }
        }
        float ps[4][3];
        {
            u64 acc[4][2];
            #pragma unroll
            for (int i = 0; i < 4; i++) { acc[i][0] = 0ull; acc[i][1] = 0ull; }
            mmk<4>(ms, Ws, r0, c0, acc);
            #pragma unroll
            for (int i = 0; i < 4; i++) {
                float2 f0 = up2(acc[i][0]);
                float2 f1 = up2(acc[i][1]);
                float h0 = silu_f(f0.x + bhs[c0]);
                float h1 = silu_f(f0.y + bhs[c0+1]);
                float h2 = silu_f(f1.x + bhs[c0+2]);
                float h3 = silu_f(f1.y + bhs[c0+3]);
                #pragma unroll
                for (int ch = 0; ch < 3; ch++)
                    ps[i][ch] = h0*w2s[c0*3+ch] + h1*w2s[(c0+1)*3+ch]
                              + h2*w2s[(c0+2)*3+ch] + h3*w2s[(c0+3)*3+ch];
            }
        }
        float my_p = 0.f, my_s0 = 0.f, my_s1 = 0.f, my_s2 = 0.f;
        #pragma unroll
        for (int i = 0; i < 4; i++) {
            float v0 = pp[i], v1 = ps[i][0], v2 = ps[i][1], v3 = ps[i][2];
            #pragma unroll
            for (int off = 16; off > 0; off >>= 1) {
                v0 += __shfl_xor_sync(0xffffffffu, v0, off);
                v1 += __shfl_xor_sync(0xffffffffu, v1, off);
                v2 += __shfl_xor_sync(0xffffffffu, v2, off);
                v3 += __shfl_xor_sync(0xffffffffu, v3, off);
            }
            if (tx == i) { my_p = v0; my_s0 = v1; my_s1 = v2; my_s2 = v3; }
        }
        if (tx < 4) {
            int e = e0 + r0 + tx;
            int r = g_er[e], c = g_ec[e];
            float psc = my_p + bp2l[0];
            float s0 = my_s0 + bs2l[0];
            float s1 = my_s1 + bs2l[1];
            float s2 = my_s2 + bs2l[2];
            float dp0 = g_pos[r*3+0] - g_pos[c*3+0];
            float dp1 = g_pos[r*3+1] - g_pos[c*3+1];
            float dp2 = g_pos[r*3+2] - g_pos[c*3+2];
            atomicAdd(&g_psum[r*3+0], dp0*psc);
            atomicAdd(&g_psum[r*3+1], dp1*psc);
            atomicAdd(&g_psum[r*3+2], dp2*psc);
            #pragma unroll
            for (int q = 0; q < 9; q++) {
                float diff = g_sh[r*9 + q] - g_sh[c*9 + q];
                float wq = (q == 0) ? s0 : (q < 4) ? s1 : s2;
                atomicAdd(&g_ssum[r*9 + q], diff*wq);
            }
        }
        __syncthreads();
    }
}

__global__ void posh_kernel() {
    int i = blockIdx.x*256 + threadIdx.x;
    if (i >= Nn) return;
    float inv = 1.0f / fmaxf(g_deg[i], 1.0f);
    #pragma unroll
    for (int q = 0; q < 3; q++) g_pos[i*3 + q] += g_psum[i*3 + q]*inv;
    #pragma unroll
    for (int q = 0; q < 9; q++) g_sh[i*9 + q] += g_ssum[i*9 + q]*inv;
}

// ---------------- readout ----------------
__global__ void pool_kernel(const int* __restrict__ batch) {
    int idx = blockIdx.x*256 + threadIdx.x;
    if (idx >= Nn*140) return;
    int i = idx / 140, c = idx % 140;
    float v;
    if (c < 128)      v = g_feat[(size_t)i*128 + c];
    else if (c < 131) v = g_pos[i*3 + (c - 128)];
    else              v = g_sh[i*9 + (c - 131)];
    atomicAdd(&g_pool[batch[i]*140 + c], v);
}

__global__ void pred_kernel(const float* __restrict__ Wpred, const float* __restrict__ bpred,
                            float* __restrict__ out) {
    int g = blockIdx.x, lane = threadIdx.x;
    float s = 0.f;
    for (int c = lane; c < 140; c += 32)
        s = fmaf(g_pool[g*140 + c], Wpred[c], s);
    #pragma unroll
    for (int off = 16; off > 0; off >>= 1)
        s += __shfl_xor_sync(0xffffffffu, s, off);
    if (lane == 0) out[g] = s + bpred[0];
}

// ---------------- host ----------------
extern "C" void kernel_launch(void* const* d_in, const int* in_sizes, int n_in,
                              void* d_out, int out_size) {
    const int*   atoms = (const int*)d_in[0];
    const int*   ei    = (const int*)d_in[1];
    const int*   batch = (const int*)d_in[2];
    const float* pos   = (const float*)d_in[3];
    const float* emb   = (const float*)d_in[4];
    const float* Wsi1  = (const float*)d_in[5];  const float* bsi1  = (const float*)d_in[6];
    const float* Wsi2  = (const float*)d_in[7];  const float* bsi2  = (const float*)d_in[8];
    const float* WsiC1 = (const float*)d_in[9];  const float* bsiC1 = (const float*)d_in[10];
    const float* WsiC2 = (const float*)d_in[11]; const float* bsiC2 = (const float*)d_in[12];
    const float* Wm1   = (const float*)d_in[13]; const float* bm1   = (const float*)d_in[14];
    const float* Wm2   = (const float*)d_in[15]; const float* bm2   = (const float*)d_in[16];
    const float* Wp1   = (const float*)d_in[17]; const float* bp1   = (const float*)d_in[18];
    const float* Wp2   = (const float*)d_in[19]; const float* bp2   = (const float*)d_in[20];
    const float* Wn1   = (const float*)d_in[21]; const float* bn1   = (const float*)d_in[22];
    const float* Wn2   = (const float*)d_in[23]; const float* bn2   = (const float*)d_in[24];
    const float* Ws1   = (const float*)d_in[25]; const float* bs1   = (const float*)d_in[26];
    const float* Ws2   = (const float*)d_in[27]; const float* bs2   = (const float*)d_in[28];
    const float* Wpred = (const float*)d_in[29]; const float* bpred = (const float*)d_in[30];
    float* out = (float*)d_out;

    cudaFuncSetAttribute(featab_kernel, cudaFuncAttributeMaxDynamicSharedMemorySize, FAB_SMEM);
    cudaFuncSetAttribute(nodeup_kernel, cudaFuncAttributeMaxDynamicSharedMemorySize, NU_SMEM);
    cudaFuncSetAttribute(edge_hm_kernel, cudaFuncAttributeMaxDynamicSharedMemorySize, E1_SMEM);
    cudaFuncSetAttribute(edge_ps_kernel, cudaFuncAttributeMaxDynamicSharedMemorySize, E2_SMEM);

    void *p_msum, *p_psum, *p_ssum, *p_deg, *p_com, *p_cnt, *p_pool, *p_pos, *p_cur;
    cudaGetSymbolAddress(&p_msum, g_msum);
    cudaGetSymbolAddress(&p_psum, g_psum);
    cudaGetSymbolAddress(&p_ssum, g_ssum);
    cudaGetSymbolAddress(&p_deg,  g_deg);
    cudaGetSymbolAddress(&p_com,  g_com);
    cudaGetSymbolAddress(&p_cnt,  g_cnt);
    cudaGetSymbolAddress(&p_pool, g_pool);
    cudaGetSymbolAddress(&p_pos,  g_pos);
    cudaGetSymbolAddress(&p_cur,  g_cursor);

    cudaMemsetAsync(p_deg,  0, Nn*4, 0);
    cudaMemsetAsync(p_com,  0, Gg*3*4, 0);
    cudaMemsetAsync(p_cnt,  0, Gg*4, 0);
    cudaMemsetAsync(p_ssum, 0, Nn*9*4, 0);
    cudaMemsetAsync(p_pool, 0, Gg*140*4, 0);
    cudaMemsetAsync(p_cur,  0, Nn*4, 0);
    cudaMemcpyAsync(p_pos, pos, Nn*3*4, cudaMemcpyDeviceToDevice, 0);

    node_init_kernel<<<(Nn*128)/256, 256>>>(atoms, emb);
    com_kernel<<<(Nn + 255)/256, 256>>>(batch);
    deg_kernel<<<(Ee + 255)/256, 256>>>(ei);
    scan_kernel<<<1, 256>>>();
    sortscatter_kernel<<<(Ee + 255)/256, 256>>>(ei);
    vocab_kernel<<<10, 128>>>(emb, Wsi1, WsiC1, bsiC1, WsiC2, bsiC2);
    edge_init_kernel<<<Ee/8, 256>>>(atoms, Wsi1, bsi1, Wsi2, bsi2);
    sh_init_kernel<<<(Nn + 255)/256, 256>>>(atoms, batch);

    int gridN = (Nn + 63)/64;   // 157

    for (int l = 0; l < Ll; l++) {
        cudaMemsetAsync(p_msum, 0, (size_t)Nn*128*4, 0);
        cudaMemsetAsync(p_psum, 0, Nn*3*4, 0);
        cudaMemsetAsync(p_ssum, 0, Nn*9*4, 0);

        featab_kernel<<<gridN, 256, FAB_SMEM>>>(
            Wm1 + (size_t)l*260*128, Wm1 + ((size_t)l*260 + 128)*128);

        edge_hm_kernel<<<296, 256, E1_SMEM>>>(
            Wm2 + (size_t)l*128*128, bm2 + l*128,
            Wm1 + ((size_t)l*260 + 256)*128, bm1 + l*128);

        edge_ps_kernel<<<148, 512, E2_SMEM>>>(
            Wp1 + (size_t)l*128*128, bp1 + l*128, Wp2 + l*128, bp2 + l,
            Ws1 + (size_t)l*128*128, bs1 + l*128, Ws2 + l*384, bs2 + l*3);

        posh_kernel<<<(Nn + 255)/256, 256>>>();

        nodeup_kernel<<<gridN, 256, NU_SMEM>>>(
            Wn1 + (size_t)l*256*128, Wn1 + ((size_t)l*256 + 128)*128,
            Wn2 + (size_t)l*128*128, bn1 + l*128, bn2 + l*128);
    }

    pool_kernel<<<(Nn*140 + 255)/256, 256>>>(batch);
    pred_kernel<<<Gg, 32>>>(Wpred, bpred, out);
}